// round 5
// baseline (speedup 1.0000x reference)
#include <cuda_runtime.h>
#include <cuda_fp16.h>
#include <math.h>
#include <stdint.h>

#define B_SZ    2
#define SEQ_L   2048
#define D_MODEL 1024
#define D_STATE 16
#define D_INNER 2048
#define DT_RANK 64
#define T_TOT   (B_SZ * SEQ_L)          // 4096 tokens

// ---------------- fp32 scratch ----------------------------------------------
__device__ float g_xz[(size_t)T_TOT * 2 * D_INNER];   // in_proj out (x_in | z)
__device__ float g_xconv[(size_t)T_TOT * D_INNER];
__device__ float g_p96[(size_t)T_TOT * 96];           // [dtr(64)|B(16)|C(16)]
__device__ float g_dt[(size_t)T_TOT * D_INNER];

// ---------------- fp16 scratch ----------------------------------------------
__device__ __half g_xh[(size_t)T_TOT * D_MODEL],  g_xl[(size_t)T_TOT * D_MODEL];
__device__ __half g_wih[(size_t)2*D_INNER*D_MODEL];
__device__ __half g_xch[(size_t)T_TOT * D_INNER], g_xcl[(size_t)T_TOT * D_INNER];
__device__ __half g_wcath[96 * D_INNER];
__device__ __half g_p96h[(size_t)T_TOT * 96],     g_p96l[(size_t)T_TOT * 96];
__device__ __half g_dtph[D_INNER * DT_RANK];
__device__ __half g_yh[(size_t)T_TOT * D_INNER];
__device__ __half g_oph[(size_t)D_MODEL*D_INNER];

// ================= helpers ==================================================
__device__ __forceinline__ uint32_t smem_u32(const void* p) {
    uint32_t a;
    asm("{ .reg .u64 t; cvta.to.shared.u64 t, %1; cvt.u32.u64 %0, t; }" : "=r"(a) : "l"(p));
    return a;
}
__device__ __forceinline__ void cp16(uint32_t dst, const void* src, uint32_t sz) {
    asm volatile("cp.async.cg.shared.global [%0], [%1], 16, %2;" :: "r"(dst), "l"(src), "r"(sz) : "memory");
}
#define CP_COMMIT()  asm volatile("cp.async.commit_group;" ::: "memory")

__device__ __forceinline__ void ldsm4(uint32_t& r0, uint32_t& r1, uint32_t& r2, uint32_t& r3, uint32_t a) {
    asm volatile("ldmatrix.sync.aligned.m8n8.x4.shared.b16 {%0,%1,%2,%3}, [%4];"
                 : "=r"(r0), "=r"(r1), "=r"(r2), "=r"(r3) : "r"(a));
}
__device__ __forceinline__ void mma16816h(float* d, const uint32_t* a, const uint32_t* b) {
    asm volatile("mma.sync.aligned.m16n8k16.row.col.f32.f16.f16.f32 "
                 "{%0,%1,%2,%3}, {%4,%5,%6,%7}, {%8,%9}, {%0,%1,%2,%3};"
                 : "+f"(d[0]), "+f"(d[1]), "+f"(d[2]), "+f"(d[3])
                 : "r"(a[0]), "r"(a[1]), "r"(a[2]), "r"(a[3]), "r"(b[0]), "r"(b[1]));
}
__device__ __forceinline__ void split1h(float v, __half& h, __half& l) {
    h = __float2half_rn(v);
    l = __float2half_rn(v - __half2float(h));
}

// ================= fp16 HMMA GEMM (optional A-lo term, 3-stage pipe) ========
//  C[M,N] = (Ah[+Al])[M,K] * Bh[N,K]^T
//  The Al correction is applied only for output columns n < lo_nlim.
//  EPI 0: fp32 | 1: softplus(acc + bias[n]) | 2: fp32 + hi/lo fp16 (guarded N)
#define RS     144
#define MATB   (128 * RS)       // 18432
#define STG    (3 * MATB)       // 55296
static const int GEMM_SMEM = 3 * STG;   // 165888, 3 stages

template<int EPI>
__global__ void __launch_bounds__(256) gemm_mma(
    const __half* __restrict__ Ah, const __half* __restrict__ Al, int lda,
    const __half* __restrict__ Bh, int ldb,
    float* __restrict__ C, int ldc, int M, int N, int K, int lo_nlim,
    const float* __restrict__ bias,
    __half* __restrict__ Chi, __half* __restrict__ Clo)
{
    extern __shared__ __align__(128) char ds[];
    const uint32_t sb = smem_u32(ds);
    const int tid = threadIdx.x, wid = tid >> 5, lane = tid & 31;
    const int m0 = blockIdx.y * 128, n0 = blockIdx.x * 128;
    const int wm = (wid & 3) * 32;
    const int wn = (wid >> 2) * 64;
    const int nbv = min(128, N - n0);
    const int NC = K >> 6;
    const bool use_lo = (Al != nullptr) && (n0 < lo_nlim);

    float d[2][8][4];
#pragma unroll
    for (int i = 0; i < 2; i++)
#pragma unroll
        for (int j = 0; j < 8; j++)
#pragma unroll
            for (int q = 0; q < 4; q++) d[i][j][q] = 0.f;

    auto load_stage = [&](int s, int c) {
        const int k0 = c << 6;
        const uint32_t base = sb + s * STG;
        for (int i = tid; i < 3072; i += 256) {
            const int mat = i >> 10;
            if (mat == 1 && !use_lo) continue;
            const int r   = (i >> 3) & 127;
            const int seg = i & 7;
            const uint32_t dst = base + mat * MATB + r * RS + seg * 16;
            const __half* mp; int ld, gr; uint32_t sz = 16;
            if (mat == 0)      { mp = Ah; ld = lda; gr = m0 + r; }
            else if (mat == 1) { mp = Al; ld = lda; gr = m0 + r; }
            else               { mp = Bh; ld = ldb; gr = n0 + r;
                                 if (r >= nbv) { sz = 0; gr = n0; } }
            cp16(dst, mp + (size_t)gr * ld + k0 + seg * 8, sz);
        }
        CP_COMMIT();
    };

    load_stage(0, 0);
    if (NC > 1) load_stage(1, 1);

    for (int c = 0; c < NC; c++) {
        if (c + 2 < NC) {
            load_stage((c + 2) % 3, c + 2);
            asm volatile("cp.async.wait_group 2;" ::: "memory");
        } else if (c + 1 < NC) {
            asm volatile("cp.async.wait_group 1;" ::: "memory");
        } else {
            asm volatile("cp.async.wait_group 0;" ::: "memory");
        }
        __syncthreads();

        const uint32_t base = sb + (c % 3) * STG;
        const uint32_t aH = base, aL = base + MATB, bH = base + 2 * MATB;
#pragma unroll
        for (int ks = 0; ks < 4; ks++) {
            const int k0 = ks * 16;
            uint32_t a_h[2][4], a_l[2][4], b_h[8][2];
            const uint32_t aoff = (wm + (lane & 15)) * RS + (k0 + ((lane >> 4) << 3)) * 2;
#pragma unroll
            for (int mi = 0; mi < 2; mi++) {
                ldsm4(a_h[mi][0], a_h[mi][1], a_h[mi][2], a_h[mi][3], aH + aoff + mi * 16 * RS);
                if (use_lo)
                    ldsm4(a_l[mi][0], a_l[mi][1], a_l[mi][2], a_l[mi][3], aL + aoff + mi * 16 * RS);
            }
            const int g = lane >> 3;
            const uint32_t boff = (wn + ((g >> 1) << 3) + (lane & 7)) * RS + (k0 + ((g & 1) << 3)) * 2;
#pragma unroll
            for (int ng = 0; ng < 4; ng++)
                ldsm4(b_h[ng*2][0], b_h[ng*2][1], b_h[ng*2+1][0], b_h[ng*2+1][1], bH + boff + ng * 16 * RS);
#pragma unroll
            for (int mi = 0; mi < 2; mi++)
#pragma unroll
                for (int ni = 0; ni < 8; ni++) {
                    mma16816h(d[mi][ni], a_h[mi], b_h[ni]);
                    if (use_lo) mma16816h(d[mi][ni], a_l[mi], b_h[ni]);
                }
        }
        __syncthreads();
    }

    // ---- epilogue ----------------------------------------------------------
#pragma unroll
    for (int mi = 0; mi < 2; mi++) {
#pragma unroll
        for (int ni = 0; ni < 8; ni++) {
            const int col = n0 + wn + ni * 8 + (lane & 3) * 2;
#pragma unroll
            for (int hf = 0; hf < 2; hf++) {
                const int row = m0 + wm + mi * 16 + (lane >> 2) + hf * 8;
                float vx = d[mi][ni][hf * 2 + 0];
                float vy = d[mi][ni][hf * 2 + 1];
                if (EPI == 1) {
                    vx += bias[col];     vy += bias[col + 1];
                    vx = (vx > 20.f) ? vx : log1pf(expf(vx));
                    vy = (vy > 20.f) ? vy : log1pf(expf(vy));
                }
                if (EPI == 2) {
                    const size_t o = (size_t)row * ldc + col;
                    if (col < N) {
                        C[o] = vx;
                        __half h, l; split1h(vx, h, l);
                        Chi[o] = h; Clo[o] = l;
                    }
                    if (col + 1 < N) {
                        C[o + 1] = vy;
                        __half h, l; split1h(vy, h, l);
                        Chi[o + 1] = h; Clo[o + 1] = l;
                    }
                } else {
                    float2 v2 = make_float2(vx, vy);
                    *(float2*)&C[(size_t)row * ldc + col] = v2;
                }
            }
        }
    }
}

// ================= small kernels ============================================
__global__ void split_kernel(const float* __restrict__ s, __half* __restrict__ h,
                             __half* __restrict__ l, int n)
{
    int i = blockIdx.x * 256 + threadIdx.x;
    if (i < n) { __half hh, ll; split1h(s[i], hh, ll); h[i] = hh; l[i] = ll; }
}

__global__ void cvt_kernel(const float* __restrict__ s, __half* __restrict__ h, int n)
{
    int i = blockIdx.x * 256 + threadIdx.x;
    if (i < n) h[i] = __float2half_rn(s[i]);
}

__global__ void conv_silu_kernel(const float* __restrict__ conv_w,
                                 const float* __restrict__ conv_b)
{
    int idx = blockIdx.x * blockDim.x + threadIdx.x;
    if (idx >= T_TOT * D_INNER) return;
    int ch  = idx % D_INNER;
    int tok = idx / D_INNER;
    int b = tok / SEQ_L, l = tok % SEQ_L;
    float acc = conv_b[ch];
#pragma unroll
    for (int j = 0; j < 4; j++) {
        int ll = l - 3 + j;
        if (ll >= 0)
            acc = fmaf(conv_w[ch * 4 + j],
                       g_xz[(size_t)(b * SEQ_L + ll) * (2 * D_INNER) + ch], acc);
    }
    float s = acc / (1.f + expf(-acc));
    g_xconv[idx] = s;
    __half h, lo; split1h(s, h, lo);
    g_xch[idx] = h; g_xcl[idx] = lo;
}

__global__ void wcat_kernel(const float* __restrict__ xp,
                            const float* __restrict__ bp,
                            const float* __restrict__ cp)
{
    int idx = blockIdx.x * blockDim.x + threadIdx.x;
    if (idx >= 96 * D_INNER) return;
    int r = idx / D_INNER, k = idx % D_INNER;
    float v;
    if (r < 64)      v = xp[r * D_INNER + k];
    else if (r < 80) v = bp[(r - 64) * D_INNER + k];
    else             v = cp[(r - 80) * D_INNER + k];
    g_wcath[idx] = __float2half_rn(v);
}

// ---------------- selective scan + D-residual + gate ------------------------
#define TCHUNK 64
__global__ void __launch_bounds__(128) scan_kernel(
    const float* __restrict__ A_log,
    const float* __restrict__ Dp)
{
    __shared__ float Xs [TCHUNK][32];
    __shared__ float DTs[TCHUNK][32];
    __shared__ float Zs [TCHUNK][32];
    __shared__ float BCs[TCHUNK][32];
    __shared__ float Ys [TCHUNK][32];

    const int b      = blockIdx.x >> 6;
    const int chBase = (blockIdx.x & 63) * 32;
    const int tid = threadIdx.x;
    const int chl = tid >> 2;
    const int sg  = tid & 3;
    const int ch  = chBase + chl;

    const float a0 = -expf(A_log[ch * D_STATE + sg * 4 + 0]);
    const float a1 = -expf(A_log[ch * D_STATE + sg * 4 + 1]);
    const float a2 = -expf(A_log[ch * D_STATE + sg * 4 + 2]);
    const float a3 = -expf(A_log[ch * D_STATE + sg * 4 + 3]);
    float h0 = 0.f, h1 = 0.f, h2 = 0.f, h3 = 0.f;

    for (int t0 = 0; t0 < SEQ_L; t0 += TCHUNK) {
        for (int i = tid; i < TCHUNK * 32; i += 128) {
            int tt = i >> 5, c = i & 31;
            size_t tok = (size_t)(b * SEQ_L + t0 + tt);
            Xs [tt][c] = g_xconv[tok * D_INNER + chBase + c];
            DTs[tt][c] = g_dt   [tok * D_INNER + chBase + c];
            Zs [tt][c] = g_xz   [tok * (2 * D_INNER) + D_INNER + chBase + c];
            BCs[tt][c] = g_p96  [tok * 96 + 64 + c];
        }
        __syncthreads();

        for (int t = 0; t < TCHUNK; t++) {
            float x  = Xs [t][chl];
            float dt = DTs[t][chl];
            float dx = dt * x;
            float4 Bv = *(const float4*)&BCs[t][sg * 4];
            float4 Cv = *(const float4*)&BCs[t][16 + sg * 4];
            h0 = fmaf(fmaf(dt, a0, 1.f), h0, dx * Bv.x);
            h1 = fmaf(fmaf(dt, a1, 1.f), h1, dx * Bv.y);
            h2 = fmaf(fmaf(dt, a2, 1.f), h2, dx * Bv.z);
            h3 = fmaf(fmaf(dt, a3, 1.f), h3, dx * Bv.w);
            float yp =  h0 * Cv.x;
            yp = fmaf(h1, Cv.y, yp);
            yp = fmaf(h2, Cv.z, yp);
            yp = fmaf(h3, Cv.w, yp);
            yp += __shfl_xor_sync(0xffffffffu, yp, 1);
            yp += __shfl_xor_sync(0xffffffffu, yp, 2);
            if (sg == 0) Ys[t][chl] = yp;
        }
        __syncthreads();

        for (int i = tid; i < TCHUNK * 32; i += 128) {
            int tt = i >> 5, c = i & 31;
            size_t tok = (size_t)(b * SEQ_L + t0 + tt);
            float yv = fmaf(Dp[chBase + c], Xs[tt][c], Ys[tt][c]);
            float z  = Zs[tt][c];
            yv *= z / (1.f + expf(-z));
            g_yh[tok * D_INNER + chBase + c] = __float2half_rn(yv);
        }
        __syncthreads();
    }
}

// ================= launch ====================================================
extern "C" void kernel_launch(void* const* d_in, const int* in_sizes, int n_in,
                              void* d_out, int out_size)
{
    const float* x          = (const float*)d_in[0];
    const float* in_proj_w  = (const float*)d_in[1];
    const float* conv_w     = (const float*)d_in[2];
    const float* conv_b     = (const float*)d_in[3];
    const float* A_log      = (const float*)d_in[4];
    const float* Dp         = (const float*)d_in[5];
    const float* dt_proj_w  = (const float*)d_in[6];
    const float* dt_proj_b  = (const float*)d_in[7];
    const float* x_proj_w   = (const float*)d_in[8];
    const float* B_proj_w   = (const float*)d_in[9];
    const float* C_proj_w   = (const float*)d_in[10];
    const float* out_proj_w = (const float*)d_in[11];
    float* out = (float*)d_out;

    cudaFuncSetAttribute(gemm_mma<0>, cudaFuncAttributeMaxDynamicSharedMemorySize, GEMM_SMEM);
    cudaFuncSetAttribute(gemm_mma<1>, cudaFuncAttributeMaxDynamicSharedMemorySize, GEMM_SMEM);
    cudaFuncSetAttribute(gemm_mma<2>, cudaFuncAttributeMaxDynamicSharedMemorySize, GEMM_SMEM);

    float *xz, *p96, *dtb;
    __half *xh, *xl, *wih, *xch, *xcl, *wcath;
    __half *p96h, *p96l, *dtph, *yh, *oph;
    cudaGetSymbolAddress((void**)&xz,    g_xz);
    cudaGetSymbolAddress((void**)&p96,   g_p96);
    cudaGetSymbolAddress((void**)&dtb,   g_dt);
    cudaGetSymbolAddress((void**)&xh,    g_xh);
    cudaGetSymbolAddress((void**)&xl,    g_xl);
    cudaGetSymbolAddress((void**)&wih,   g_wih);
    cudaGetSymbolAddress((void**)&xch,   g_xch);
    cudaGetSymbolAddress((void**)&xcl,   g_xcl);
    cudaGetSymbolAddress((void**)&wcath, g_wcath);
    cudaGetSymbolAddress((void**)&p96h,  g_p96h);
    cudaGetSymbolAddress((void**)&p96l,  g_p96l);
    cudaGetSymbolAddress((void**)&dtph,  g_dtph);
    cudaGetSymbolAddress((void**)&yh,    g_yh);
    cudaGetSymbolAddress((void**)&oph,   g_oph);

    // splits / conversions
    split_kernel<<<(T_TOT * D_MODEL + 255) / 256, 256>>>(x, xh, xl, T_TOT * D_MODEL);
    cvt_kernel<<<(2 * D_INNER * D_MODEL + 255) / 256, 256>>>(in_proj_w, wih, 2 * D_INNER * D_MODEL);
    cvt_kernel<<<(D_INNER * DT_RANK + 255) / 256, 256>>>(dt_proj_w, dtph, D_INNER * DT_RANK);
    cvt_kernel<<<(D_MODEL * D_INNER + 255) / 256, 256>>>(out_proj_w, oph, D_MODEL * D_INNER);
    wcat_kernel<<<(96 * D_INNER + 255) / 256, 256>>>(x_proj_w, B_proj_w, C_proj_w);

    // 1) in_proj: lo-correction only for the x_in half (n < 2048)
    {
        dim3 grid((2 * D_INNER) / 128, T_TOT / 128);
        gemm_mma<0><<<grid, 256, GEMM_SMEM>>>(xh, xl, D_MODEL, wih, D_MODEL,
                                              xz, 2 * D_INNER, T_TOT, 2 * D_INNER, D_MODEL,
                                              D_INNER, nullptr, nullptr, nullptr);
    }
    // 2) conv + silu (+ split)
    conv_silu_kernel<<<(T_TOT * D_INNER + 255) / 256, 256>>>(conv_w, conv_b);

    // 3) p96 = xconv @ wcat^T  (fp32 + hi/lo)
    {
        dim3 grid(1, T_TOT / 128);
        gemm_mma<2><<<grid, 256, GEMM_SMEM>>>(xch, xcl, D_INNER, wcath, D_INNER,
                                              p96, 96, T_TOT, 96, D_INNER,
                                              1 << 30, nullptr, p96h, p96l);
    }
    // 4) dt = softplus(dtr @ dt_proj_w^T + b)
    {
        dim3 grid(D_INNER / 128, T_TOT / 128);
        gemm_mma<1><<<grid, 256, GEMM_SMEM>>>(p96h, p96l, 96, dtph, DT_RANK,
                                              dtb, D_INNER, T_TOT, D_INNER, DT_RANK,
                                              1 << 30, dt_proj_b, nullptr, nullptr);
    }
    // 5) scan
    scan_kernel<<<B_SZ * (D_INNER / 32), 128>>>(A_log, Dp);

    // 6) out_proj: single-term fp16
    {
        dim3 grid(D_MODEL / 128, T_TOT / 128);
        gemm_mma<0><<<grid, 256, GEMM_SMEM>>>(yh, nullptr, D_INNER, oph, D_INNER,
                                              out, D_MODEL, T_TOT, D_MODEL, D_INNER,
                                              0, nullptr, nullptr, nullptr);
    }
}

// round 6
// speedup vs baseline: 1.1040x; 1.1040x over previous
#include <cuda_runtime.h>
#include <cuda_fp16.h>
#include <math.h>
#include <stdint.h>

#define B_SZ    2
#define SEQ_L   2048
#define D_MODEL 1024
#define D_STATE 16
#define D_INNER 2048
#define DT_RANK 64
#define T_TOT   (B_SZ * SEQ_L)          // 4096 tokens

// ---------------- fp32 scratch ----------------------------------------------
__device__ float g_xz[(size_t)T_TOT * 2 * D_INNER];   // in_proj out (x_in | z)
__device__ float g_xconv[(size_t)T_TOT * D_INNER];
__device__ float g_p96[(size_t)T_TOT * 96];           // [dtr(64)|B(16)|C(16)]
__device__ float g_dt[(size_t)T_TOT * D_INNER];

// ---------------- fp16 scratch ----------------------------------------------
__device__ __half g_xh[(size_t)T_TOT * D_MODEL],  g_xl[(size_t)T_TOT * D_MODEL];
__device__ __half g_wih[(size_t)2*D_INNER*D_MODEL];
__device__ __half g_xch[(size_t)T_TOT * D_INNER], g_xcl[(size_t)T_TOT * D_INNER];
__device__ __half g_wcath[96 * D_INNER];
__device__ __half g_p96h[(size_t)T_TOT * 96],     g_p96l[(size_t)T_TOT * 96];
__device__ __half g_dtph[D_INNER * DT_RANK];
__device__ __half g_yh[(size_t)T_TOT * D_INNER];
__device__ __half g_oph[(size_t)D_MODEL*D_INNER];

// ================= helpers ==================================================
__device__ __forceinline__ uint32_t smem_u32(const void* p) {
    uint32_t a;
    asm("{ .reg .u64 t; cvta.to.shared.u64 t, %1; cvt.u32.u64 %0, t; }" : "=r"(a) : "l"(p));
    return a;
}
__device__ __forceinline__ void cp16(uint32_t dst, const void* src, uint32_t sz) {
    asm volatile("cp.async.cg.shared.global [%0], [%1], 16, %2;" :: "r"(dst), "l"(src), "r"(sz) : "memory");
}
#define CP_COMMIT()  asm volatile("cp.async.commit_group;" ::: "memory")

__device__ __forceinline__ void ldsm4(uint32_t& r0, uint32_t& r1, uint32_t& r2, uint32_t& r3, uint32_t a) {
    asm volatile("ldmatrix.sync.aligned.m8n8.x4.shared.b16 {%0,%1,%2,%3}, [%4];"
                 : "=r"(r0), "=r"(r1), "=r"(r2), "=r"(r3) : "r"(a));
}
__device__ __forceinline__ void mma16816h(float* d, const uint32_t* a, const uint32_t* b) {
    asm volatile("mma.sync.aligned.m16n8k16.row.col.f32.f16.f16.f32 "
                 "{%0,%1,%2,%3}, {%4,%5,%6,%7}, {%8,%9}, {%0,%1,%2,%3};"
                 : "+f"(d[0]), "+f"(d[1]), "+f"(d[2]), "+f"(d[3])
                 : "r"(a[0]), "r"(a[1]), "r"(a[2]), "r"(a[3]), "r"(b[0]), "r"(b[1]));
}
__device__ __forceinline__ void split1h(float v, __half& h, __half& l) {
    h = __float2half_rn(v);
    l = __float2half_rn(v - __half2float(h));
}

// ================= fp16 HMMA GEMM (optional A-lo term, 2-stage pipe) ========
//  C[M,N] = (Ah[+Al])[M,K] * Bh[N,K]^T
//  The Al correction is applied only for output columns n < lo_nlim.
//  EPI 0: fp32 | 1: softplus(acc + bias[n]) | 2: fp32 + hi/lo fp16 (guarded N)
//  smem: 2 stages x (Ah|Al|Bh) x (128 rows x 144B) = 110592 -> 2 CTAs/SM
#define RS     144
#define MATB   (128 * RS)       // 18432
#define STG    (3 * MATB)       // 55296
static const int GEMM_SMEM = 2 * STG;   // 110592

template<int EPI>
__global__ void __launch_bounds__(256) gemm_mma(
    const __half* __restrict__ Ah, const __half* __restrict__ Al, int lda,
    const __half* __restrict__ Bh, int ldb,
    float* __restrict__ C, int ldc, int M, int N, int K, int lo_nlim,
    const float* __restrict__ bias,
    __half* __restrict__ Chi, __half* __restrict__ Clo)
{
    extern __shared__ __align__(128) char ds[];
    const uint32_t sb = smem_u32(ds);
    const int tid = threadIdx.x, wid = tid >> 5, lane = tid & 31;
    const int m0 = blockIdx.y * 128, n0 = blockIdx.x * 128;
    const int wm = (wid & 3) * 32;
    const int wn = (wid >> 2) * 64;
    const int nbv = min(128, N - n0);
    const int NC = K >> 6;
    const bool use_lo = (Al != nullptr) && (n0 < lo_nlim);

    float d[2][8][4];
#pragma unroll
    for (int i = 0; i < 2; i++)
#pragma unroll
        for (int j = 0; j < 8; j++)
#pragma unroll
            for (int q = 0; q < 4; q++) d[i][j][q] = 0.f;

    auto load_stage = [&](int s, int c) {
        const int k0 = c << 6;
        const uint32_t base = sb + s * STG;
        for (int i = tid; i < 3072; i += 256) {
            const int mat = i >> 10;
            if (mat == 1 && !use_lo) continue;
            const int r   = (i >> 3) & 127;
            const int seg = i & 7;
            const uint32_t dst = base + mat * MATB + r * RS + seg * 16;
            const __half* mp; int ld, gr; uint32_t sz = 16;
            if (mat == 0)      { mp = Ah; ld = lda; gr = m0 + r; }
            else if (mat == 1) { mp = Al; ld = lda; gr = m0 + r; }
            else               { mp = Bh; ld = ldb; gr = n0 + r;
                                 if (r >= nbv) { sz = 0; gr = n0; } }
            cp16(dst, mp + (size_t)gr * ld + k0 + seg * 8, sz);
        }
        CP_COMMIT();
    };

    load_stage(0, 0);

    for (int c = 0; c < NC; c++) {
        const int s = c & 1;
        if (c + 1 < NC) {
            load_stage(s ^ 1, c + 1);
            asm volatile("cp.async.wait_group 1;" ::: "memory");
        } else {
            asm volatile("cp.async.wait_group 0;" ::: "memory");
        }
        __syncthreads();

        const uint32_t base = sb + s * STG;
        const uint32_t aH = base, aL = base + MATB, bH = base + 2 * MATB;
#pragma unroll
        for (int ks = 0; ks < 4; ks++) {
            const int k0 = ks * 16;
            uint32_t a_h[2][4], a_l[2][4], b_h[8][2];
            const uint32_t aoff = (wm + (lane & 15)) * RS + (k0 + ((lane >> 4) << 3)) * 2;
#pragma unroll
            for (int mi = 0; mi < 2; mi++) {
                ldsm4(a_h[mi][0], a_h[mi][1], a_h[mi][2], a_h[mi][3], aH + aoff + mi * 16 * RS);
                if (use_lo)
                    ldsm4(a_l[mi][0], a_l[mi][1], a_l[mi][2], a_l[mi][3], aL + aoff + mi * 16 * RS);
            }
            const int g = lane >> 3;
            const uint32_t boff = (wn + ((g >> 1) << 3) + (lane & 7)) * RS + (k0 + ((g & 1) << 3)) * 2;
#pragma unroll
            for (int ng = 0; ng < 4; ng++)
                ldsm4(b_h[ng*2][0], b_h[ng*2][1], b_h[ng*2+1][0], b_h[ng*2+1][1], bH + boff + ng * 16 * RS);
#pragma unroll
            for (int mi = 0; mi < 2; mi++)
#pragma unroll
                for (int ni = 0; ni < 8; ni++) {
                    mma16816h(d[mi][ni], a_h[mi], b_h[ni]);
                    if (use_lo) mma16816h(d[mi][ni], a_l[mi], b_h[ni]);
                }
        }
        __syncthreads();
    }

    // ---- epilogue ----------------------------------------------------------
#pragma unroll
    for (int mi = 0; mi < 2; mi++) {
#pragma unroll
        for (int ni = 0; ni < 8; ni++) {
            const int col = n0 + wn + ni * 8 + (lane & 3) * 2;
#pragma unroll
            for (int hf = 0; hf < 2; hf++) {
                const int row = m0 + wm + mi * 16 + (lane >> 2) + hf * 8;
                float vx = d[mi][ni][hf * 2 + 0];
                float vy = d[mi][ni][hf * 2 + 1];
                if (EPI == 1) {
                    vx += bias[col];     vy += bias[col + 1];
                    vx = (vx > 20.f) ? vx : log1pf(expf(vx));
                    vy = (vy > 20.f) ? vy : log1pf(expf(vy));
                }
                if (EPI == 2) {
                    const size_t o = (size_t)row * ldc + col;
                    if (col < N) {
                        C[o] = vx;
                        __half h, l; split1h(vx, h, l);
                        Chi[o] = h; Clo[o] = l;
                    }
                    if (col + 1 < N) {
                        C[o + 1] = vy;
                        __half h, l; split1h(vy, h, l);
                        Chi[o + 1] = h; Clo[o + 1] = l;
                    }
                } else {
                    float2 v2 = make_float2(vx, vy);
                    *(float2*)&C[(size_t)row * ldc + col] = v2;
                }
            }
        }
    }
}

// ================= small kernels ============================================
__global__ void split_kernel(const float* __restrict__ s, __half* __restrict__ h,
                             __half* __restrict__ l, int n)
{
    int i = blockIdx.x * 256 + threadIdx.x;
    if (i < n) { __half hh, ll; split1h(s[i], hh, ll); h[i] = hh; l[i] = ll; }
}

__global__ void cvt_kernel(const float* __restrict__ s, __half* __restrict__ h, int n)
{
    int i = blockIdx.x * 256 + threadIdx.x;
    if (i < n) h[i] = __float2half_rn(s[i]);
}

__global__ void conv_silu_kernel(const float* __restrict__ conv_w,
                                 const float* __restrict__ conv_b)
{
    int idx = blockIdx.x * blockDim.x + threadIdx.x;
    if (idx >= T_TOT * D_INNER) return;
    int ch  = idx % D_INNER;
    int tok = idx / D_INNER;
    int b = tok / SEQ_L, l = tok % SEQ_L;
    float acc = conv_b[ch];
#pragma unroll
    for (int j = 0; j < 4; j++) {
        int ll = l - 3 + j;
        if (ll >= 0)
            acc = fmaf(conv_w[ch * 4 + j],
                       g_xz[(size_t)(b * SEQ_L + ll) * (2 * D_INNER) + ch], acc);
    }
    float s = acc / (1.f + expf(-acc));
    g_xconv[idx] = s;
    __half h, lo; split1h(s, h, lo);
    g_xch[idx] = h; g_xcl[idx] = lo;
}

__global__ void wcat_kernel(const float* __restrict__ xp,
                            const float* __restrict__ bp,
                            const float* __restrict__ cp)
{
    int idx = blockIdx.x * blockDim.x + threadIdx.x;
    if (idx >= 96 * D_INNER) return;
    int r = idx / D_INNER, k = idx % D_INNER;
    float v;
    if (r < 64)      v = xp[r * D_INNER + k];
    else if (r < 80) v = bp[(r - 64) * D_INNER + k];
    else             v = cp[(r - 80) * D_INNER + k];
    g_wcath[idx] = __float2half_rn(v);
}

// ---------------- selective scan + D-residual + gate ------------------------
#define TCHUNK 64
__global__ void __launch_bounds__(128) scan_kernel(
    const float* __restrict__ A_log,
    const float* __restrict__ Dp)
{
    __shared__ float Xs [TCHUNK][32];
    __shared__ float DTs[TCHUNK][32];
    __shared__ float Zs [TCHUNK][32];
    __shared__ float BCs[TCHUNK][32];
    __shared__ float Ys [TCHUNK][32];

    const int b      = blockIdx.x >> 6;
    const int chBase = (blockIdx.x & 63) * 32;
    const int tid = threadIdx.x;
    const int chl = tid >> 2;
    const int sg  = tid & 3;
    const int ch  = chBase + chl;

    const float a0 = -expf(A_log[ch * D_STATE + sg * 4 + 0]);
    const float a1 = -expf(A_log[ch * D_STATE + sg * 4 + 1]);
    const float a2 = -expf(A_log[ch * D_STATE + sg * 4 + 2]);
    const float a3 = -expf(A_log[ch * D_STATE + sg * 4 + 3]);
    float h0 = 0.f, h1 = 0.f, h2 = 0.f, h3 = 0.f;

    for (int t0 = 0; t0 < SEQ_L; t0 += TCHUNK) {
        for (int i = tid; i < TCHUNK * 32; i += 128) {
            int tt = i >> 5, c = i & 31;
            size_t tok = (size_t)(b * SEQ_L + t0 + tt);
            Xs [tt][c] = g_xconv[tok * D_INNER + chBase + c];
            DTs[tt][c] = g_dt   [tok * D_INNER + chBase + c];
            Zs [tt][c] = g_xz   [tok * (2 * D_INNER) + D_INNER + chBase + c];
            BCs[tt][c] = g_p96  [tok * 96 + 64 + c];
        }
        __syncthreads();

        for (int t = 0; t < TCHUNK; t++) {
            float x  = Xs [t][chl];
            float dt = DTs[t][chl];
            float dx = dt * x;
            float4 Bv = *(const float4*)&BCs[t][sg * 4];
            float4 Cv = *(const float4*)&BCs[t][16 + sg * 4];
            h0 = fmaf(fmaf(dt, a0, 1.f), h0, dx * Bv.x);
            h1 = fmaf(fmaf(dt, a1, 1.f), h1, dx * Bv.y);
            h2 = fmaf(fmaf(dt, a2, 1.f), h2, dx * Bv.z);
            h3 = fmaf(fmaf(dt, a3, 1.f), h3, dx * Bv.w);
            float yp =  h0 * Cv.x;
            yp = fmaf(h1, Cv.y, yp);
            yp = fmaf(h2, Cv.z, yp);
            yp = fmaf(h3, Cv.w, yp);
            yp += __shfl_xor_sync(0xffffffffu, yp, 1);
            yp += __shfl_xor_sync(0xffffffffu, yp, 2);
            if (sg == 0) Ys[t][chl] = yp;
        }
        __syncthreads();

        for (int i = tid; i < TCHUNK * 32; i += 128) {
            int tt = i >> 5, c = i & 31;
            size_t tok = (size_t)(b * SEQ_L + t0 + tt);
            float yv = fmaf(Dp[chBase + c], Xs[tt][c], Ys[tt][c]);
            float z  = Zs[tt][c];
            yv *= z / (1.f + expf(-z));
            g_yh[tok * D_INNER + chBase + c] = __float2half_rn(yv);
        }
        __syncthreads();
    }
}

// ================= launch ====================================================
extern "C" void kernel_launch(void* const* d_in, const int* in_sizes, int n_in,
                              void* d_out, int out_size)
{
    const float* x          = (const float*)d_in[0];
    const float* in_proj_w  = (const float*)d_in[1];
    const float* conv_w     = (const float*)d_in[2];
    const float* conv_b     = (const float*)d_in[3];
    const float* A_log      = (const float*)d_in[4];
    const float* Dp         = (const float*)d_in[5];
    const float* dt_proj_w  = (const float*)d_in[6];
    const float* dt_proj_b  = (const float*)d_in[7];
    const float* x_proj_w   = (const float*)d_in[8];
    const float* B_proj_w   = (const float*)d_in[9];
    const float* C_proj_w   = (const float*)d_in[10];
    const float* out_proj_w = (const float*)d_in[11];
    float* out = (float*)d_out;

    cudaFuncSetAttribute(gemm_mma<0>, cudaFuncAttributeMaxDynamicSharedMemorySize, GEMM_SMEM);
    cudaFuncSetAttribute(gemm_mma<1>, cudaFuncAttributeMaxDynamicSharedMemorySize, GEMM_SMEM);
    cudaFuncSetAttribute(gemm_mma<2>, cudaFuncAttributeMaxDynamicSharedMemorySize, GEMM_SMEM);

    float *xz, *p96, *dtb;
    __half *xh, *xl, *wih, *xch, *xcl, *wcath;
    __half *p96h, *p96l, *dtph, *yh, *oph;
    cudaGetSymbolAddress((void**)&xz,    g_xz);
    cudaGetSymbolAddress((void**)&p96,   g_p96);
    cudaGetSymbolAddress((void**)&dtb,   g_dt);
    cudaGetSymbolAddress((void**)&xh,    g_xh);
    cudaGetSymbolAddress((void**)&xl,    g_xl);
    cudaGetSymbolAddress((void**)&wih,   g_wih);
    cudaGetSymbolAddress((void**)&xch,   g_xch);
    cudaGetSymbolAddress((void**)&xcl,   g_xcl);
    cudaGetSymbolAddress((void**)&wcath, g_wcath);
    cudaGetSymbolAddress((void**)&p96h,  g_p96h);
    cudaGetSymbolAddress((void**)&p96l,  g_p96l);
    cudaGetSymbolAddress((void**)&dtph,  g_dtph);
    cudaGetSymbolAddress((void**)&yh,    g_yh);
    cudaGetSymbolAddress((void**)&oph,   g_oph);

    // splits / conversions
    split_kernel<<<(T_TOT * D_MODEL + 255) / 256, 256>>>(x, xh, xl, T_TOT * D_MODEL);
    cvt_kernel<<<(2 * D_INNER * D_MODEL + 255) / 256, 256>>>(in_proj_w, wih, 2 * D_INNER * D_MODEL);
    cvt_kernel<<<(D_INNER * DT_RANK + 255) / 256, 256>>>(dt_proj_w, dtph, D_INNER * DT_RANK);
    cvt_kernel<<<(D_MODEL * D_INNER + 255) / 256, 256>>>(out_proj_w, oph, D_MODEL * D_INNER);
    wcat_kernel<<<(96 * D_INNER + 255) / 256, 256>>>(x_proj_w, B_proj_w, C_proj_w);

    // 1) in_proj: lo-correction only for the x_in half (n < 2048)
    {
        dim3 grid((2 * D_INNER) / 128, T_TOT / 128);
        gemm_mma<0><<<grid, 256, GEMM_SMEM>>>(xh, xl, D_MODEL, wih, D_MODEL,
                                              xz, 2 * D_INNER, T_TOT, 2 * D_INNER, D_MODEL,
                                              D_INNER, nullptr, nullptr, nullptr);
    }
    // 2) conv + silu (+ split)
    conv_silu_kernel<<<(T_TOT * D_INNER + 255) / 256, 256>>>(conv_w, conv_b);

    // 3) p96 = xconv @ wcat^T  (fp32 + hi/lo)
    {
        dim3 grid(1, T_TOT / 128);
        gemm_mma<2><<<grid, 256, GEMM_SMEM>>>(xch, xcl, D_INNER, wcath, D_INNER,
                                              p96, 96, T_TOT, 96, D_INNER,
                                              1 << 30, nullptr, p96h, p96l);
    }
    // 4) dt = softplus(dtr @ dt_proj_w^T + b)
    {
        dim3 grid(D_INNER / 128, T_TOT / 128);
        gemm_mma<1><<<grid, 256, GEMM_SMEM>>>(p96h, p96l, 96, dtph, DT_RANK,
                                              dtb, D_INNER, T_TOT, D_INNER, DT_RANK,
                                              1 << 30, dt_proj_b, nullptr, nullptr);
    }
    // 5) scan
    scan_kernel<<<B_SZ * (D_INNER / 32), 128>>>(A_log, Dp);

    // 6) out_proj: single-term fp16
    {
        dim3 grid(D_MODEL / 128, T_TOT / 128);
        gemm_mma<0><<<grid, 256, GEMM_SMEM>>>(yh, nullptr, D_INNER, oph, D_INNER,
                                              out, D_MODEL, T_TOT, D_MODEL, D_INNER,
                                              0, nullptr, nullptr, nullptr);
    }
}

// round 7
// speedup vs baseline: 1.2756x; 1.1554x over previous
#include <cuda_runtime.h>
#include <cuda_fp16.h>
#include <math.h>
#include <stdint.h>

#define B_SZ    2
#define SEQ_L   2048
#define D_MODEL 1024
#define D_STATE 16
#define D_INNER 2048
#define DT_RANK 64
#define T_TOT   (B_SZ * SEQ_L)          // 4096 tokens

// ---------------- fp32 scratch ----------------------------------------------
__device__ float g_xz[(size_t)T_TOT * 2 * D_INNER];   // in_proj out (x_in | z)
__device__ float g_xconv[(size_t)T_TOT * D_INNER];
__device__ float g_p96[(size_t)T_TOT * 96];           // [dtr(64)|B(16)|C(16)]
__device__ float g_dt[(size_t)T_TOT * D_INNER];

// ---------------- fp16 scratch ----------------------------------------------
__device__ __half g_xh[(size_t)T_TOT * D_MODEL],  g_xl[(size_t)T_TOT * D_MODEL];
__device__ __half g_wih[(size_t)2*D_INNER*D_MODEL];
__device__ __half g_xch[(size_t)T_TOT * D_INNER], g_xcl[(size_t)T_TOT * D_INNER];
__device__ __half g_wcath[96 * D_INNER];
__device__ __half g_p96h[(size_t)T_TOT * 96],     g_p96l[(size_t)T_TOT * 96];
__device__ __half g_dtph[D_INNER * DT_RANK];
__device__ __half g_yh[(size_t)T_TOT * D_INNER];
__device__ __half g_oph[(size_t)D_MODEL*D_INNER];

// ================= helpers ==================================================
__device__ __forceinline__ uint32_t smem_u32(const void* p) {
    uint32_t a;
    asm("{ .reg .u64 t; cvta.to.shared.u64 t, %1; cvt.u32.u64 %0, t; }" : "=r"(a) : "l"(p));
    return a;
}
__device__ __forceinline__ void cp16(uint32_t dst, const void* src, uint32_t sz) {
    asm volatile("cp.async.cg.shared.global [%0], [%1], 16, %2;" :: "r"(dst), "l"(src), "r"(sz) : "memory");
}
#define CP_COMMIT()  asm volatile("cp.async.commit_group;" ::: "memory")

__device__ __forceinline__ void ldsm4(uint32_t& r0, uint32_t& r1, uint32_t& r2, uint32_t& r3, uint32_t a) {
    asm volatile("ldmatrix.sync.aligned.m8n8.x4.shared.b16 {%0,%1,%2,%3}, [%4];"
                 : "=r"(r0), "=r"(r1), "=r"(r2), "=r"(r3) : "r"(a));
}
__device__ __forceinline__ void mma16816h(float* d, const uint32_t* a, const uint32_t* b) {
    asm volatile("mma.sync.aligned.m16n8k16.row.col.f32.f16.f16.f32 "
                 "{%0,%1,%2,%3}, {%4,%5,%6,%7}, {%8,%9}, {%0,%1,%2,%3};"
                 : "+f"(d[0]), "+f"(d[1]), "+f"(d[2]), "+f"(d[3])
                 : "r"(a[0]), "r"(a[1]), "r"(a[2]), "r"(a[3]), "r"(b[0]), "r"(b[1]));
}
__device__ __forceinline__ void split1h(float v, __half& h, __half& l) {
    h = __float2half_rn(v);
    l = __float2half_rn(v - __half2float(h));
}

// ================= fp16 HMMA GEMM (compile-time A-lo term, 2-stage pipe) ====
//  C[M,N] = (Ah[+Al])[M,K] * Bh[N,K]^T
//  EPI 0: fp32 | 1: softplus(acc + bias[n]) | 2: fp32 + hi/lo fp16 (guarded N)
//  smem: 2 stages x (Ah|Al|Bh) x (128 rows x 144B) = 110592 -> 2 CTAs/SM
#define RS     144
#define MATB   (128 * RS)       // 18432
#define STG    (3 * MATB)       // 55296
static const int GEMM_SMEM = 2 * STG;   // 110592

template<int EPI, int USE_LO>
__global__ void __launch_bounds__(256) gemm_mma(
    const __half* __restrict__ Ah, const __half* __restrict__ Al, int lda,
    const __half* __restrict__ Bh, int ldb,
    float* __restrict__ C, int ldc, int M, int N, int K,
    const float* __restrict__ bias,
    __half* __restrict__ Chi, __half* __restrict__ Clo)
{
    extern __shared__ __align__(128) char ds[];
    const uint32_t sb = smem_u32(ds);
    const int tid = threadIdx.x, wid = tid >> 5, lane = tid & 31;
    const int m0 = blockIdx.y * 128, n0 = blockIdx.x * 128;
    const int wm = (wid & 3) * 32;
    const int wn = (wid >> 2) * 64;
    const int nbv = min(128, N - n0);
    const int NC = K >> 6;

    float d[2][8][4];
#pragma unroll
    for (int i = 0; i < 2; i++)
#pragma unroll
        for (int j = 0; j < 8; j++)
#pragma unroll
            for (int q = 0; q < 4; q++) d[i][j][q] = 0.f;

    constexpr int NCP = USE_LO ? 3072 : 2048;   // cp.async slots per stage
    auto load_stage = [&](int s, int c) {
        const int k0 = c << 6;
        const uint32_t base = sb + s * STG;
        for (int i = tid; i < NCP; i += 256) {
            // mats: 0 = Ah, 1 = Al (only if USE_LO), last = Bh
            const int mat = i >> 10;
            const int r   = (i >> 3) & 127;
            const int seg = i & 7;
            const __half* mp; int ld, gr; uint32_t sz = 16; uint32_t moff;
            if (mat == 0) { mp = Ah; ld = lda; gr = m0 + r; moff = 0; }
            else if (USE_LO && mat == 1) { mp = Al; ld = lda; gr = m0 + r; moff = MATB; }
            else { mp = Bh; ld = ldb; gr = n0 + r; moff = 2 * MATB;
                   if (r >= nbv) { sz = 0; gr = n0; } }
            const uint32_t dst = base + moff + r * RS + seg * 16;
            cp16(dst, mp + (size_t)gr * ld + k0 + seg * 8, sz);
        }
        CP_COMMIT();
    };

    load_stage(0, 0);

    for (int c = 0; c < NC; c++) {
        const int s = c & 1;
        if (c + 1 < NC) {
            load_stage(s ^ 1, c + 1);
            asm volatile("cp.async.wait_group 1;" ::: "memory");
        } else {
            asm volatile("cp.async.wait_group 0;" ::: "memory");
        }
        __syncthreads();

        const uint32_t base = sb + s * STG;
        const uint32_t aH = base, aL = base + MATB, bH = base + 2 * MATB;
#pragma unroll
        for (int ks = 0; ks < 4; ks++) {
            const int k0 = ks * 16;
            uint32_t a_h[2][4], a_l[2][4], b_h[8][2];
            const uint32_t aoff = (wm + (lane & 15)) * RS + (k0 + ((lane >> 4) << 3)) * 2;
#pragma unroll
            for (int mi = 0; mi < 2; mi++) {
                ldsm4(a_h[mi][0], a_h[mi][1], a_h[mi][2], a_h[mi][3], aH + aoff + mi * 16 * RS);
                if (USE_LO)
                    ldsm4(a_l[mi][0], a_l[mi][1], a_l[mi][2], a_l[mi][3], aL + aoff + mi * 16 * RS);
            }
            const int g = lane >> 3;
            const uint32_t boff = (wn + ((g >> 1) << 3) + (lane & 7)) * RS + (k0 + ((g & 1) << 3)) * 2;
#pragma unroll
            for (int ng = 0; ng < 4; ng++)
                ldsm4(b_h[ng*2][0], b_h[ng*2][1], b_h[ng*2+1][0], b_h[ng*2+1][1], bH + boff + ng * 16 * RS);
#pragma unroll
            for (int mi = 0; mi < 2; mi++)
#pragma unroll
                for (int ni = 0; ni < 8; ni++) {
                    mma16816h(d[mi][ni], a_h[mi], b_h[ni]);
                    if (USE_LO) mma16816h(d[mi][ni], a_l[mi], b_h[ni]);
                }
        }
        __syncthreads();
    }

    // ---- epilogue ----------------------------------------------------------
#pragma unroll
    for (int mi = 0; mi < 2; mi++) {
#pragma unroll
        for (int ni = 0; ni < 8; ni++) {
            const int col = n0 + wn + ni * 8 + (lane & 3) * 2;
#pragma unroll
            for (int hf = 0; hf < 2; hf++) {
                const int row = m0 + wm + mi * 16 + (lane >> 2) + hf * 8;
                float vx = d[mi][ni][hf * 2 + 0];
                float vy = d[mi][ni][hf * 2 + 1];
                if (EPI == 1) {
                    vx += bias[col];     vy += bias[col + 1];
                    vx = (vx > 20.f) ? vx : log1pf(expf(vx));
                    vy = (vy > 20.f) ? vy : log1pf(expf(vy));
                }
                if (EPI == 2) {
                    const size_t o = (size_t)row * ldc + col;
                    if (col < N) {
                        C[o] = vx;
                        __half h, l; split1h(vx, h, l);
                        Chi[o] = h; Clo[o] = l;
                    }
                    if (col + 1 < N) {
                        C[o + 1] = vy;
                        __half h, l; split1h(vy, h, l);
                        Chi[o + 1] = h; Clo[o + 1] = l;
                    }
                } else {
                    float2 v2 = make_float2(vx, vy);
                    *(float2*)&C[(size_t)row * ldc + col] = v2;
                }
            }
        }
    }
}

// ================= small kernels ============================================
__global__ void split_kernel(const float* __restrict__ s, __half* __restrict__ h,
                             __half* __restrict__ l, int n)
{
    int i = blockIdx.x * 256 + threadIdx.x;
    if (i < n) { __half hh, ll; split1h(s[i], hh, ll); h[i] = hh; l[i] = ll; }
}

__global__ void cvt_kernel(const float* __restrict__ s, __half* __restrict__ h, int n)
{
    int i = blockIdx.x * 256 + threadIdx.x;
    if (i < n) h[i] = __float2half_rn(s[i]);
}

__global__ void conv_silu_kernel(const float* __restrict__ conv_w,
                                 const float* __restrict__ conv_b)
{
    int idx = blockIdx.x * blockDim.x + threadIdx.x;
    if (idx >= T_TOT * D_INNER) return;
    int ch  = idx % D_INNER;
    int tok = idx / D_INNER;
    int b = tok / SEQ_L, l = tok % SEQ_L;
    float acc = conv_b[ch];
#pragma unroll
    for (int j = 0; j < 4; j++) {
        int ll = l - 3 + j;
        if (ll >= 0)
            acc = fmaf(conv_w[ch * 4 + j],
                       g_xz[(size_t)(b * SEQ_L + ll) * (2 * D_INNER) + ch], acc);
    }
    float s = acc / (1.f + expf(-acc));
    g_xconv[idx] = s;
    __half h, lo; split1h(s, h, lo);
    g_xch[idx] = h; g_xcl[idx] = lo;
}

__global__ void wcat_kernel(const float* __restrict__ xp,
                            const float* __restrict__ bp,
                            const float* __restrict__ cp)
{
    int idx = blockIdx.x * blockDim.x + threadIdx.x;
    if (idx >= 96 * D_INNER) return;
    int r = idx / D_INNER, k = idx % D_INNER;
    float v;
    if (r < 64)      v = xp[r * D_INNER + k];
    else if (r < 80) v = bp[(r - 64) * D_INNER + k];
    else             v = cp[(r - 80) * D_INNER + k];
    g_wcath[idx] = __float2half_rn(v);
}

// ---------------- selective scan + D-residual + gate ------------------------
#define TCHUNK 64
__global__ void __launch_bounds__(128) scan_kernel(
    const float* __restrict__ A_log,
    const float* __restrict__ Dp)
{
    __shared__ float Xs [TCHUNK][32];
    __shared__ float DTs[TCHUNK][32];
    __shared__ float Zs [TCHUNK][32];
    __shared__ float BCs[TCHUNK][32];
    __shared__ float Ys [TCHUNK][32];

    const int b      = blockIdx.x >> 6;
    const int chBase = (blockIdx.x & 63) * 32;
    const int tid = threadIdx.x;
    const int chl = tid >> 2;
    const int sg  = tid & 3;
    const int ch  = chBase + chl;

    const float a0 = -expf(A_log[ch * D_STATE + sg * 4 + 0]);
    const float a1 = -expf(A_log[ch * D_STATE + sg * 4 + 1]);
    const float a2 = -expf(A_log[ch * D_STATE + sg * 4 + 2]);
    const float a3 = -expf(A_log[ch * D_STATE + sg * 4 + 3]);
    float h0 = 0.f, h1 = 0.f, h2 = 0.f, h3 = 0.f;

    for (int t0 = 0; t0 < SEQ_L; t0 += TCHUNK) {
        for (int i = tid; i < TCHUNK * 32; i += 128) {
            int tt = i >> 5, c = i & 31;
            size_t tok = (size_t)(b * SEQ_L + t0 + tt);
            Xs [tt][c] = g_xconv[tok * D_INNER + chBase + c];
            DTs[tt][c] = g_dt   [tok * D_INNER + chBase + c];
            Zs [tt][c] = g_xz   [tok * (2 * D_INNER) + D_INNER + chBase + c];
            BCs[tt][c] = g_p96  [tok * 96 + 64 + c];
        }
        __syncthreads();

        for (int t = 0; t < TCHUNK; t++) {
            float x  = Xs [t][chl];
            float dt = DTs[t][chl];
            float dx = dt * x;
            float4 Bv = *(const float4*)&BCs[t][sg * 4];
            float4 Cv = *(const float4*)&BCs[t][16 + sg * 4];
            h0 = fmaf(fmaf(dt, a0, 1.f), h0, dx * Bv.x);
            h1 = fmaf(fmaf(dt, a1, 1.f), h1, dx * Bv.y);
            h2 = fmaf(fmaf(dt, a2, 1.f), h2, dx * Bv.z);
            h3 = fmaf(fmaf(dt, a3, 1.f), h3, dx * Bv.w);
            float yp =  h0 * Cv.x;
            yp = fmaf(h1, Cv.y, yp);
            yp = fmaf(h2, Cv.z, yp);
            yp = fmaf(h3, Cv.w, yp);
            yp += __shfl_xor_sync(0xffffffffu, yp, 1);
            yp += __shfl_xor_sync(0xffffffffu, yp, 2);
            if (sg == 0) Ys[t][chl] = yp;
        }
        __syncthreads();

        for (int i = tid; i < TCHUNK * 32; i += 128) {
            int tt = i >> 5, c = i & 31;
            size_t tok = (size_t)(b * SEQ_L + t0 + tt);
            float yv = fmaf(Dp[chBase + c], Xs[tt][c], Ys[tt][c]);
            float z  = Zs[tt][c];
            yv *= z / (1.f + expf(-z));
            g_yh[tok * D_INNER + chBase + c] = __float2half_rn(yv);
        }
        __syncthreads();
    }
}

// ================= launch ====================================================
extern "C" void kernel_launch(void* const* d_in, const int* in_sizes, int n_in,
                              void* d_out, int out_size)
{
    const float* x          = (const float*)d_in[0];
    const float* in_proj_w  = (const float*)d_in[1];
    const float* conv_w     = (const float*)d_in[2];
    const float* conv_b     = (const float*)d_in[3];
    const float* A_log      = (const float*)d_in[4];
    const float* Dp         = (const float*)d_in[5];
    const float* dt_proj_w  = (const float*)d_in[6];
    const float* dt_proj_b  = (const float*)d_in[7];
    const float* x_proj_w   = (const float*)d_in[8];
    const float* B_proj_w   = (const float*)d_in[9];
    const float* C_proj_w   = (const float*)d_in[10];
    const float* out_proj_w = (const float*)d_in[11];
    float* out = (float*)d_out;

    cudaFuncSetAttribute(gemm_mma<0,1>, cudaFuncAttributeMaxDynamicSharedMemorySize, GEMM_SMEM);
    cudaFuncSetAttribute(gemm_mma<0,0>, cudaFuncAttributeMaxDynamicSharedMemorySize, GEMM_SMEM);
    cudaFuncSetAttribute(gemm_mma<1,1>, cudaFuncAttributeMaxDynamicSharedMemorySize, GEMM_SMEM);
    cudaFuncSetAttribute(gemm_mma<2,1>, cudaFuncAttributeMaxDynamicSharedMemorySize, GEMM_SMEM);

    float *xz, *p96, *dtb;
    __half *xh, *xl, *wih, *xch, *xcl, *wcath;
    __half *p96h, *p96l, *dtph, *yh, *oph;
    cudaGetSymbolAddress((void**)&xz,    g_xz);
    cudaGetSymbolAddress((void**)&p96,   g_p96);
    cudaGetSymbolAddress((void**)&dtb,   g_dt);
    cudaGetSymbolAddress((void**)&xh,    g_xh);
    cudaGetSymbolAddress((void**)&xl,    g_xl);
    cudaGetSymbolAddress((void**)&wih,   g_wih);
    cudaGetSymbolAddress((void**)&xch,   g_xch);
    cudaGetSymbolAddress((void**)&xcl,   g_xcl);
    cudaGetSymbolAddress((void**)&wcath, g_wcath);
    cudaGetSymbolAddress((void**)&p96h,  g_p96h);
    cudaGetSymbolAddress((void**)&p96l,  g_p96l);
    cudaGetSymbolAddress((void**)&dtph,  g_dtph);
    cudaGetSymbolAddress((void**)&yh,    g_yh);
    cudaGetSymbolAddress((void**)&oph,   g_oph);

    // splits / conversions
    split_kernel<<<(T_TOT * D_MODEL + 255) / 256, 256>>>(x, xh, xl, T_TOT * D_MODEL);
    cvt_kernel<<<(2 * D_INNER * D_MODEL + 255) / 256, 256>>>(in_proj_w, wih, 2 * D_INNER * D_MODEL);
    cvt_kernel<<<(D_INNER * DT_RANK + 255) / 256, 256>>>(dt_proj_w, dtph, D_INNER * DT_RANK);
    cvt_kernel<<<(D_MODEL * D_INNER + 255) / 256, 256>>>(out_proj_w, oph, D_MODEL * D_INNER);
    wcat_kernel<<<(96 * D_INNER + 255) / 256, 256>>>(x_proj_w, B_proj_w, C_proj_w);

    // 1a) in_proj x-half (2-term A)
    {
        dim3 grid(D_INNER / 128, T_TOT / 128);
        gemm_mma<0,1><<<grid, 256, GEMM_SMEM>>>(xh, xl, D_MODEL, wih, D_MODEL,
                                                xz, 2 * D_INNER, T_TOT, D_INNER, D_MODEL,
                                                nullptr, nullptr, nullptr);
    }
    // 1b) in_proj z-half (1-term A)
    {
        dim3 grid(D_INNER / 128, T_TOT / 128);
        gemm_mma<0,0><<<grid, 256, GEMM_SMEM>>>(xh, nullptr, D_MODEL,
                                                wih + (size_t)D_INNER * D_MODEL, D_MODEL,
                                                xz + D_INNER, 2 * D_INNER, T_TOT, D_INNER, D_MODEL,
                                                nullptr, nullptr, nullptr);
    }
    // 2) conv + silu (+ split)
    conv_silu_kernel<<<(T_TOT * D_INNER + 255) / 256, 256>>>(conv_w, conv_b);

    // 3) p96 = xconv @ wcat^T  (fp32 + hi/lo)
    {
        dim3 grid(1, T_TOT / 128);
        gemm_mma<2,1><<<grid, 256, GEMM_SMEM>>>(xch, xcl, D_INNER, wcath, D_INNER,
                                                p96, 96, T_TOT, 96, D_INNER,
                                                nullptr, p96h, p96l);
    }
    // 4) dt = softplus(dtr @ dt_proj_w^T + b)
    {
        dim3 grid(D_INNER / 128, T_TOT / 128);
        gemm_mma<1,1><<<grid, 256, GEMM_SMEM>>>(p96h, p96l, 96, dtph, DT_RANK,
                                                dtb, D_INNER, T_TOT, D_INNER, DT_RANK,
                                                dt_proj_b, nullptr, nullptr);
    }
    // 5) scan
    scan_kernel<<<B_SZ * (D_INNER / 32), 128>>>(A_log, Dp);

    // 6) out_proj: single-term fp16
    {
        dim3 grid(D_MODEL / 128, T_TOT / 128);
        gemm_mma<0,0><<<grid, 256, GEMM_SMEM>>>(yh, nullptr, D_INNER, oph, D_INNER,
                                                out, D_MODEL, T_TOT, D_MODEL, D_INNER,
                                                nullptr, nullptr, nullptr);
    }
}

// round 9
// speedup vs baseline: 1.4135x; 1.1081x over previous
#include <cuda_runtime.h>
#include <cuda_fp16.h>
#include <math.h>
#include <stdint.h>

#define B_SZ    2
#define SEQ_L   2048
#define D_MODEL 1024
#define D_STATE 16
#define D_INNER 2048
#define DT_RANK 64
#define T_TOT   (B_SZ * SEQ_L)          // 4096 tokens

// ---------------- fp32 scratch ----------------------------------------------
__device__ float g_xz[(size_t)T_TOT * 2 * D_INNER];   // in_proj out (x_in | z)
__device__ float g_xconv[(size_t)T_TOT * D_INNER];
__device__ float g_p96[(size_t)T_TOT * 96];           // [dtr(64)|B(16)|C(16)]
__device__ float g_dt[(size_t)T_TOT * D_INNER];

// ---------------- fp16 scratch ----------------------------------------------
__device__ __half g_xh[(size_t)T_TOT * D_MODEL];
__device__ __half g_wih[(size_t)2*D_INNER*D_MODEL];
__device__ __half g_xch[(size_t)T_TOT * D_INNER], g_xcl[(size_t)T_TOT * D_INNER];
__device__ __half g_wcath[96 * D_INNER];
__device__ __half g_p96h[(size_t)T_TOT * 96],     g_p96l[(size_t)T_TOT * 96];
__device__ __half g_dtph[D_INNER * DT_RANK];
__device__ __half g_yh[(size_t)T_TOT * D_INNER];
__device__ __half g_oph[(size_t)D_MODEL*D_INNER];

// ================= helpers ==================================================
__device__ __forceinline__ uint32_t smem_u32(const void* p) {
    uint32_t a;
    asm("{ .reg .u64 t; cvta.to.shared.u64 t, %1; cvt.u32.u64 %0, t; }" : "=r"(a) : "l"(p));
    return a;
}
__device__ __forceinline__ void cp16(uint32_t dst, const void* src, uint32_t sz) {
    asm volatile("cp.async.cg.shared.global [%0], [%1], 16, %2;" :: "r"(dst), "l"(src), "r"(sz) : "memory");
}
#define CP_COMMIT()  asm volatile("cp.async.commit_group;" ::: "memory")

__device__ __forceinline__ void ldsm4(uint32_t& r0, uint32_t& r1, uint32_t& r2, uint32_t& r3, uint32_t a) {
    asm volatile("ldmatrix.sync.aligned.m8n8.x4.shared.b16 {%0,%1,%2,%3}, [%4];"
                 : "=r"(r0), "=r"(r1), "=r"(r2), "=r"(r3) : "r"(a));
}
__device__ __forceinline__ void mma16816h(float* d, const uint32_t* a, const uint32_t* b) {
    asm volatile("mma.sync.aligned.m16n8k16.row.col.f32.f16.f16.f32 "
                 "{%0,%1,%2,%3}, {%4,%5,%6,%7}, {%8,%9}, {%0,%1,%2,%3};"
                 : "+f"(d[0]), "+f"(d[1]), "+f"(d[2]), "+f"(d[3])
                 : "r"(a[0]), "r"(a[1]), "r"(a[2]), "r"(a[3]), "r"(b[0]), "r"(b[1]));
}
__device__ __forceinline__ void split1h(float v, __half& h, __half& l) {
    h = __float2half_rn(v);
    l = __float2half_rn(v - __half2float(h));
}

// ================= fp16 HMMA GEMM (compile-time A-lo term, 2-stage pipe) ====
//  C[M,N] = (Ah[+Al])[M,K] * Bh[N,K]^T
//  EPI 0: fp32 | 1: softplus(acc + bias[n]) | 2: fp32 + hi/lo fp16 (guarded N)
//  smem: 2 stages x (Ah|Al|Bh) x (128 rows x 144B) = 110592 -> 2 CTAs/SM
#define RS     144
#define MATB   (128 * RS)       // 18432
#define STG    (3 * MATB)       // 55296
static const int GEMM_SMEM = 2 * STG;   // 110592

template<int EPI, int USE_LO>
__global__ void __launch_bounds__(256) gemm_mma(
    const __half* __restrict__ Ah, const __half* __restrict__ Al, int lda,
    const __half* __restrict__ Bh, int ldb,
    float* __restrict__ C, int ldc, int M, int N, int K,
    const float* __restrict__ bias,
    __half* __restrict__ Chi, __half* __restrict__ Clo)
{
    extern __shared__ __align__(128) char ds[];
    const uint32_t sb = smem_u32(ds);
    const int tid = threadIdx.x, wid = tid >> 5, lane = tid & 31;
    const int m0 = blockIdx.y * 128, n0 = blockIdx.x * 128;
    const int wm = (wid & 3) * 32;
    const int wn = (wid >> 2) * 64;
    const int nbv = min(128, N - n0);
    const int NC = K >> 6;

    float d[2][8][4];
#pragma unroll
    for (int i = 0; i < 2; i++)
#pragma unroll
        for (int j = 0; j < 8; j++)
#pragma unroll
            for (int q = 0; q < 4; q++) d[i][j][q] = 0.f;

    constexpr int NCP = USE_LO ? 3072 : 2048;   // cp.async slots per stage
    auto load_stage = [&](int s, int c) {
        const int k0 = c << 6;
        const uint32_t base = sb + s * STG;
        for (int i = tid; i < NCP; i += 256) {
            const int mat = i >> 10;
            const int r   = (i >> 3) & 127;
            const int seg = i & 7;
            const __half* mp; int ld, gr; uint32_t sz = 16; uint32_t moff;
            if (mat == 0) { mp = Ah; ld = lda; gr = m0 + r; moff = 0; }
            else if (USE_LO && mat == 1) { mp = Al; ld = lda; gr = m0 + r; moff = MATB; }
            else { mp = Bh; ld = ldb; gr = n0 + r; moff = 2 * MATB;
                   if (r >= nbv) { sz = 0; gr = n0; } }
            const uint32_t dst = base + moff + r * RS + seg * 16;
            cp16(dst, mp + (size_t)gr * ld + k0 + seg * 8, sz);
        }
        CP_COMMIT();
    };

    load_stage(0, 0);

    for (int c = 0; c < NC; c++) {
        const int s = c & 1;
        if (c + 1 < NC) {
            load_stage(s ^ 1, c + 1);
            asm volatile("cp.async.wait_group 1;" ::: "memory");
        } else {
            asm volatile("cp.async.wait_group 0;" ::: "memory");
        }
        __syncthreads();

        const uint32_t base = sb + s * STG;
        const uint32_t aH = base, aL = base + MATB, bH = base + 2 * MATB;
#pragma unroll
        for (int ks = 0; ks < 4; ks++) {
            const int k0 = ks * 16;
            uint32_t a_h[2][4], a_l[2][4], b_h[8][2];
            const uint32_t aoff = (wm + (lane & 15)) * RS + (k0 + ((lane >> 4) << 3)) * 2;
#pragma unroll
            for (int mi = 0; mi < 2; mi++) {
                ldsm4(a_h[mi][0], a_h[mi][1], a_h[mi][2], a_h[mi][3], aH + aoff + mi * 16 * RS);
                if (USE_LO)
                    ldsm4(a_l[mi][0], a_l[mi][1], a_l[mi][2], a_l[mi][3], aL + aoff + mi * 16 * RS);
            }
            const int g = lane >> 3;
            const uint32_t boff = (wn + ((g >> 1) << 3) + (lane & 7)) * RS + (k0 + ((g & 1) << 3)) * 2;
#pragma unroll
            for (int ng = 0; ng < 4; ng++)
                ldsm4(b_h[ng*2][0], b_h[ng*2][1], b_h[ng*2+1][0], b_h[ng*2+1][1], bH + boff + ng * 16 * RS);
#pragma unroll
            for (int mi = 0; mi < 2; mi++)
#pragma unroll
                for (int ni = 0; ni < 8; ni++) {
                    mma16816h(d[mi][ni], a_h[mi], b_h[ni]);
                    if (USE_LO) mma16816h(d[mi][ni], a_l[mi], b_h[ni]);
                }
        }
        __syncthreads();
    }

    // ---- epilogue ----------------------------------------------------------
#pragma unroll
    for (int mi = 0; mi < 2; mi++) {
#pragma unroll
        for (int ni = 0; ni < 8; ni++) {
            const int col = n0 + wn + ni * 8 + (lane & 3) * 2;
#pragma unroll
            for (int hf = 0; hf < 2; hf++) {
                const int row = m0 + wm + mi * 16 + (lane >> 2) + hf * 8;
                float vx = d[mi][ni][hf * 2 + 0];
                float vy = d[mi][ni][hf * 2 + 1];
                if (EPI == 1) {
                    vx += bias[col];     vy += bias[col + 1];
                    vx = (vx > 20.f) ? vx : log1pf(expf(vx));
                    vy = (vy > 20.f) ? vy : log1pf(expf(vy));
                }
                if (EPI == 2) {
                    const size_t o = (size_t)row * ldc + col;
                    if (col < N) {
                        C[o] = vx;
                        __half h, l; split1h(vx, h, l);
                        Chi[o] = h; Clo[o] = l;
                    }
                    if (col + 1 < N) {
                        C[o + 1] = vy;
                        __half h, l; split1h(vy, h, l);
                        Chi[o + 1] = h; Clo[o + 1] = l;
                    }
                } else {
                    float2 v2 = make_float2(vx, vy);
                    *(float2*)&C[(size_t)row * ldc + col] = v2;
                }
            }
        }
    }
}

// ================= fused preprocessing (one launch) =========================
//  seg0: x -> xh (cvt)            4,194,304
//  seg1: in_proj_w -> wih (cvt)   4,194,304
//  seg2: out_proj_w -> oph (cvt)  2,097,152
//  seg3: dt_proj_w -> dtph (cvt)    131,072
//  seg4: wcat (x/B/C proj concat)   196,608
#define PRE_S0 (T_TOT * D_MODEL)
#define PRE_S1 (2 * D_INNER * D_MODEL)
#define PRE_S2 (D_MODEL * D_INNER)
#define PRE_S3 (D_INNER * DT_RANK)
#define PRE_S4 (96 * D_INNER)
#define PRE_TOT (PRE_S0 + PRE_S1 + PRE_S2 + PRE_S3 + PRE_S4)

__global__ void prep_kernel(const float* __restrict__ x,
                            const float* __restrict__ wi,
                            const float* __restrict__ wo,
                            const float* __restrict__ dtp,
                            const float* __restrict__ xp,
                            const float* __restrict__ bp,
                            const float* __restrict__ cp)
{
    int i = blockIdx.x * 256 + threadIdx.x;
    if (i < PRE_S0) { g_xh[i] = __float2half_rn(x[i]); return; }
    i -= PRE_S0;
    if (i < PRE_S1) { g_wih[i] = __float2half_rn(wi[i]); return; }
    i -= PRE_S1;
    if (i < PRE_S2) { g_oph[i] = __float2half_rn(wo[i]); return; }
    i -= PRE_S2;
    if (i < PRE_S3) { g_dtph[i] = __float2half_rn(dtp[i]); return; }
    i -= PRE_S3;
    if (i < PRE_S4) {
        int r = i / D_INNER, k = i % D_INNER;
        float v;
        if (r < 64)      v = xp[r * D_INNER + k];
        else if (r < 80) v = bp[(r - 64) * D_INNER + k];
        else             v = cp[(r - 80) * D_INNER + k];
        g_wcath[i] = __float2half_rn(v);
    }
}

// ================= conv + silu + hi/lo split ================================
__global__ void conv_silu_kernel(const float* __restrict__ conv_w,
                                 const float* __restrict__ conv_b)
{
    int idx = blockIdx.x * blockDim.x + threadIdx.x;
    if (idx >= T_TOT * D_INNER) return;
    int ch  = idx % D_INNER;
    int tok = idx / D_INNER;
    int b = tok / SEQ_L, l = tok % SEQ_L;
    float acc = conv_b[ch];
#pragma unroll
    for (int j = 0; j < 4; j++) {
        int ll = l - 3 + j;
        if (ll >= 0)
            acc = fmaf(conv_w[ch * 4 + j],
                       g_xz[(size_t)(b * SEQ_L + ll) * (2 * D_INNER) + ch], acc);
    }
    float s = acc / (1.f + expf(-acc));
    g_xconv[idx] = s;
    __half h, lo; split1h(s, h, lo);
    g_xch[idx] = h; g_xcl[idx] = lo;
}

// ---------------- selective scan + D-residual + gate ------------------------
#define TCHUNK 64
__global__ void __launch_bounds__(128) scan_kernel(
    const float* __restrict__ A_log,
    const float* __restrict__ Dp)
{
    __shared__ float Xs [TCHUNK][32];
    __shared__ float DTs[TCHUNK][32];
    __shared__ float Zs [TCHUNK][32];
    __shared__ float BCs[TCHUNK][32];
    __shared__ float Ys [TCHUNK][32];

    const int b      = blockIdx.x >> 6;
    const int chBase = (blockIdx.x & 63) * 32;
    const int tid = threadIdx.x;
    const int chl = tid >> 2;
    const int sg  = tid & 3;
    const int ch  = chBase + chl;

    const float a0 = -expf(A_log[ch * D_STATE + sg * 4 + 0]);
    const float a1 = -expf(A_log[ch * D_STATE + sg * 4 + 1]);
    const float a2 = -expf(A_log[ch * D_STATE + sg * 4 + 2]);
    const float a3 = -expf(A_log[ch * D_STATE + sg * 4 + 3]);
    float h0 = 0.f, h1 = 0.f, h2 = 0.f, h3 = 0.f;

    for (int t0 = 0; t0 < SEQ_L; t0 += TCHUNK) {
        for (int i = tid; i < TCHUNK * 32; i += 128) {
            int tt = i >> 5, c = i & 31;
            size_t tok = (size_t)(b * SEQ_L + t0 + tt);
            Xs [tt][c] = g_xconv[tok * D_INNER + chBase + c];
            DTs[tt][c] = g_dt   [tok * D_INNER + chBase + c];
            Zs [tt][c] = g_xz   [tok * (2 * D_INNER) + D_INNER + chBase + c];
            BCs[tt][c] = g_p96  [tok * 96 + 64 + c];
        }
        __syncthreads();

        for (int t = 0; t < TCHUNK; t++) {
            float x  = Xs [t][chl];
            float dt = DTs[t][chl];
            float dx = dt * x;
            float4 Bv = *(const float4*)&BCs[t][sg * 4];
            float4 Cv = *(const float4*)&BCs[t][16 + sg * 4];
            h0 = fmaf(fmaf(dt, a0, 1.f), h0, dx * Bv.x);
            h1 = fmaf(fmaf(dt, a1, 1.f), h1, dx * Bv.y);
            h2 = fmaf(fmaf(dt, a2, 1.f), h2, dx * Bv.z);
            h3 = fmaf(fmaf(dt, a3, 1.f), h3, dx * Bv.w);
            float yp =  h0 * Cv.x;
            yp = fmaf(h1, Cv.y, yp);
            yp = fmaf(h2, Cv.z, yp);
            yp = fmaf(h3, Cv.w, yp);
            yp += __shfl_xor_sync(0xffffffffu, yp, 1);
            yp += __shfl_xor_sync(0xffffffffu, yp, 2);
            if (sg == 0) Ys[t][chl] = yp;
        }
        __syncthreads();

        for (int i = tid; i < TCHUNK * 32; i += 128) {
            int tt = i >> 5, c = i & 31;
            size_t tok = (size_t)(b * SEQ_L + t0 + tt);
            float yv = fmaf(Dp[chBase + c], Xs[tt][c], Ys[tt][c]);
            float z  = Zs[tt][c];
            yv *= z / (1.f + expf(-z));
            g_yh[tok * D_INNER + chBase + c] = __float2half_rn(yv);
        }
        __syncthreads();
    }
}

// ================= launch ====================================================
extern "C" void kernel_launch(void* const* d_in, const int* in_sizes, int n_in,
                              void* d_out, int out_size)
{
    const float* x          = (const float*)d_in[0];
    const float* in_proj_w  = (const float*)d_in[1];
    const float* conv_w     = (const float*)d_in[2];
    const float* conv_b     = (const float*)d_in[3];
    const float* A_log      = (const float*)d_in[4];
    const float* Dp         = (const float*)d_in[5];
    const float* dt_proj_w  = (const float*)d_in[6];
    const float* dt_proj_b  = (const float*)d_in[7];
    const float* x_proj_w   = (const float*)d_in[8];
    const float* B_proj_w   = (const float*)d_in[9];
    const float* C_proj_w   = (const float*)d_in[10];
    const float* out_proj_w = (const float*)d_in[11];
    float* out = (float*)d_out;

    cudaFuncSetAttribute(gemm_mma<0,0>, cudaFuncAttributeMaxDynamicSharedMemorySize, GEMM_SMEM);
    cudaFuncSetAttribute(gemm_mma<1,1>, cudaFuncAttributeMaxDynamicSharedMemorySize, GEMM_SMEM);
    cudaFuncSetAttribute(gemm_mma<2,1>, cudaFuncAttributeMaxDynamicSharedMemorySize, GEMM_SMEM);

    float *xz, *p96, *dtb;
    __half *xh, *wih, *xch, *xcl, *wcath;
    __half *p96h, *p96l, *dtph, *yh, *oph;
    cudaGetSymbolAddress((void**)&xz,    g_xz);
    cudaGetSymbolAddress((void**)&p96,   g_p96);
    cudaGetSymbolAddress((void**)&dtb,   g_dt);
    cudaGetSymbolAddress((void**)&xh,    g_xh);
    cudaGetSymbolAddress((void**)&wih,   g_wih);
    cudaGetSymbolAddress((void**)&xch,   g_xch);
    cudaGetSymbolAddress((void**)&xcl,   g_xcl);
    cudaGetSymbolAddress((void**)&wcath, g_wcath);
    cudaGetSymbolAddress((void**)&p96h,  g_p96h);
    cudaGetSymbolAddress((void**)&p96l,  g_p96l);
    cudaGetSymbolAddress((void**)&dtph,  g_dtph);
    cudaGetSymbolAddress((void**)&yh,    g_yh);
    cudaGetSymbolAddress((void**)&oph,   g_oph);

    // 0) fused preprocessing (all cvt + wcat in one launch)
    prep_kernel<<<(PRE_TOT + 255) / 256, 256>>>(x, in_proj_w, out_proj_w,
                                                dt_proj_w, x_proj_w, B_proj_w, C_proj_w);

    // 1) in_proj (single 1-term fp16 GEMM over the full 4096 output)
    {
        dim3 grid((2 * D_INNER) / 128, T_TOT / 128);
        gemm_mma<0,0><<<grid, 256, GEMM_SMEM>>>(xh, nullptr, D_MODEL, wih, D_MODEL,
                                                xz, 2 * D_INNER, T_TOT, 2 * D_INNER, D_MODEL,
                                                nullptr, nullptr, nullptr);
    }
    // 2) conv + silu (+ hi/lo split)
    conv_silu_kernel<<<(T_TOT * D_INNER + 255) / 256, 256>>>(conv_w, conv_b);

    // 3) p96 = xconv @ wcat^T  (fp32 + hi/lo, 2-term A)
    {
        dim3 grid(1, T_TOT / 128);
        gemm_mma<2,1><<<grid, 256, GEMM_SMEM>>>(xch, xcl, D_INNER, wcath, D_INNER,
                                                p96, 96, T_TOT, 96, D_INNER,
                                                nullptr, p96h, p96l);
    }
    // 4) dt = softplus(dtr @ dt_proj_w^T + b)  (2-term A)
    {
        dim3 grid(D_INNER / 128, T_TOT / 128);
        gemm_mma<1,1><<<grid, 256, GEMM_SMEM>>>(p96h, p96l, 96, dtph, DT_RANK,
                                                dtb, D_INNER, T_TOT, D_INNER, DT_RANK,
                                                dt_proj_b, nullptr, nullptr);
    }
    // 5) scan
    scan_kernel<<<B_SZ * (D_INNER / 32), 128>>>(A_log, Dp);

    // 6) out_proj (1-term)
    {
        dim3 grid(D_MODEL / 128, T_TOT / 128);
        gemm_mma<0,0><<<grid, 256, GEMM_SMEM>>>(yh, nullptr, D_INNER, oph, D_INNER,
                                                out, D_MODEL, T_TOT, D_MODEL, D_INNER,
                                                nullptr, nullptr, nullptr);
    }
}

// round 13
// speedup vs baseline: 1.5309x; 1.0830x over previous
#include <cuda_runtime.h>
#include <cuda_fp16.h>
#include <math.h>
#include <stdint.h>

#define B_SZ    2
#define SEQ_L   2048
#define D_MODEL 1024
#define D_STATE 16
#define D_INNER 2048
#define DT_RANK 64
#define T_TOT   (B_SZ * SEQ_L)          // 4096 tokens
#define KSPLIT  4
#define KSLICE  (D_INNER / KSPLIT)      // 512

// ---------------- fp32 scratch ----------------------------------------------
__device__ float g_xz[(size_t)T_TOT * 2 * D_INNER];   // in_proj out (x_in | z)
__device__ float g_xconv[(size_t)T_TOT * D_INNER];
__device__ float g_p96[(size_t)T_TOT * 96];           // [dtr(64)|B(16)|C(16)]
__device__ float g_p96part[(size_t)KSPLIT * T_TOT * 96];
__device__ float g_dt[(size_t)T_TOT * D_INNER];

// ---------------- fp16 scratch ----------------------------------------------
__device__ __half g_xh[(size_t)T_TOT * D_MODEL];
__device__ __half g_wih[(size_t)2*D_INNER*D_MODEL];
__device__ __half g_xch[(size_t)T_TOT * D_INNER], g_xcl[(size_t)T_TOT * D_INNER];
__device__ __half g_wcath[96 * D_INNER];
__device__ __half g_p96h[(size_t)T_TOT * 96],     g_p96l[(size_t)T_TOT * 96];
__device__ __half g_dtph[D_INNER * DT_RANK];
__device__ __half g_yh[(size_t)T_TOT * D_INNER];
__device__ __half g_oph[(size_t)D_MODEL*D_INNER];

// ================= helpers ==================================================
__device__ __forceinline__ uint32_t smem_u32(const void* p) {
    uint32_t a;
    asm("{ .reg .u64 t; cvta.to.shared.u64 t, %1; cvt.u32.u64 %0, t; }" : "=r"(a) : "l"(p));
    return a;
}
__device__ __forceinline__ void cp16(uint32_t dst, const void* src, uint32_t sz) {
    asm volatile("cp.async.cg.shared.global [%0], [%1], 16, %2;" :: "r"(dst), "l"(src), "r"(sz) : "memory");
}
#define CP_COMMIT()  asm volatile("cp.async.commit_group;" ::: "memory")

__device__ __forceinline__ void ldsm4(uint32_t& r0, uint32_t& r1, uint32_t& r2, uint32_t& r3, uint32_t a) {
    asm volatile("ldmatrix.sync.aligned.m8n8.x4.shared.b16 {%0,%1,%2,%3}, [%4];"
                 : "=r"(r0), "=r"(r1), "=r"(r2), "=r"(r3) : "r"(a));
}
__device__ __forceinline__ void mma16816h(float* d, const uint32_t* a, const uint32_t* b) {
    asm volatile("mma.sync.aligned.m16n8k16.row.col.f32.f16.f16.f32 "
                 "{%0,%1,%2,%3}, {%4,%5,%6,%7}, {%8,%9}, {%0,%1,%2,%3};"
                 : "+f"(d[0]), "+f"(d[1]), "+f"(d[2]), "+f"(d[3])
                 : "r"(a[0]), "r"(a[1]), "r"(a[2]), "r"(a[3]), "r"(b[0]), "r"(b[1]));
}
__device__ __forceinline__ void split1h(float v, __half& h, __half& l) {
    h = __float2half_rn(v);
    l = __float2half_rn(v - __half2float(h));
}

// ================= fp16 HMMA GEMM (compile-time A-lo term, 2-stage pipe) ====
//  C[M,N] = (Ah[+Al])[M,K] * Bh[N,K]^T
//  EPI 0: fp32 | 1: softplus(acc + bias[n]) | 2: fp32 + hi/lo fp16 (guarded N)
//  EPI 3: split-K partials -> C[(blockIdx.z*M + row)*ldc + col] (guarded N)
//  smem: 2 stages x (Ah|Al|Bh) x (128 rows x 144B) = 110592 -> 2 CTAs/SM
#define RS     144
#define MATB   (128 * RS)       // 18432
#define STG    (3 * MATB)       // 55296
static const int GEMM_SMEM = 2 * STG;   // 110592

template<int EPI, int USE_LO>
__global__ void __launch_bounds__(256) gemm_mma(
    const __half* __restrict__ Ah, const __half* __restrict__ Al, int lda,
    const __half* __restrict__ Bh, int ldb,
    float* __restrict__ C, int ldc, int M, int N, int K,
    const float* __restrict__ bias,
    __half* __restrict__ Chi, __half* __restrict__ Clo)
{
    extern __shared__ __align__(128) char ds[];
    const uint32_t sb = smem_u32(ds);
    const int tid = threadIdx.x, wid = tid >> 5, lane = tid & 31;
    const int m0 = blockIdx.y * 128, n0 = blockIdx.x * 128;
    const int wm = (wid & 3) * 32;
    const int wn = (wid >> 2) * 64;
    const int nbv = min(128, N - n0);
    const int NC = K >> 6;

    if (EPI == 3) {                    // split-K: this CTA covers one K-slice
        const int koff = blockIdx.z * K;
        Ah += koff; if (USE_LO) Al += koff; Bh += koff;
    }

    float d[2][8][4];
#pragma unroll
    for (int i = 0; i < 2; i++)
#pragma unroll
        for (int j = 0; j < 8; j++)
#pragma unroll
            for (int q = 0; q < 4; q++) d[i][j][q] = 0.f;

    constexpr int NCP = USE_LO ? 3072 : 2048;   // cp.async slots per stage
    auto load_stage = [&](int s, int c) {
        const int k0 = c << 6;
        const uint32_t base = sb + s * STG;
        for (int i = tid; i < NCP; i += 256) {
            const int mat = i >> 10;
            const int r   = (i >> 3) & 127;
            const int seg = i & 7;
            const __half* mp; int ld, gr; uint32_t sz = 16; uint32_t moff;
            if (mat == 0) { mp = Ah; ld = lda; gr = m0 + r; moff = 0; }
            else if (USE_LO && mat == 1) { mp = Al; ld = lda; gr = m0 + r; moff = MATB; }
            else { mp = Bh; ld = ldb; gr = n0 + r; moff = 2 * MATB;
                   if (r >= nbv) { sz = 0; gr = n0; } }
            const uint32_t dst = base + moff + r * RS + seg * 16;
            cp16(dst, mp + (size_t)gr * ld + k0 + seg * 8, sz);
        }
        CP_COMMIT();
    };

    load_stage(0, 0);

    for (int c = 0; c < NC; c++) {
        const int s = c & 1;
        if (c + 1 < NC) {
            load_stage(s ^ 1, c + 1);
            asm volatile("cp.async.wait_group 1;" ::: "memory");
        } else {
            asm volatile("cp.async.wait_group 0;" ::: "memory");
        }
        __syncthreads();

        const uint32_t base = sb + s * STG;
        const uint32_t aH = base, aL = base + MATB, bH = base + 2 * MATB;
#pragma unroll
        for (int ks = 0; ks < 4; ks++) {
            const int k0 = ks * 16;
            uint32_t a_h[2][4], a_l[2][4], b_h[8][2];
            const uint32_t aoff = (wm + (lane & 15)) * RS + (k0 + ((lane >> 4) << 3)) * 2;
#pragma unroll
            for (int mi = 0; mi < 2; mi++) {
                ldsm4(a_h[mi][0], a_h[mi][1], a_h[mi][2], a_h[mi][3], aH + aoff + mi * 16 * RS);
                if (USE_LO)
                    ldsm4(a_l[mi][0], a_l[mi][1], a_l[mi][2], a_l[mi][3], aL + aoff + mi * 16 * RS);
            }
            const int g = lane >> 3;
            const uint32_t boff = (wn + ((g >> 1) << 3) + (lane & 7)) * RS + (k0 + ((g & 1) << 3)) * 2;
#pragma unroll
            for (int ng = 0; ng < 4; ng++)
                ldsm4(b_h[ng*2][0], b_h[ng*2][1], b_h[ng*2+1][0], b_h[ng*2+1][1], bH + boff + ng * 16 * RS);
#pragma unroll
            for (int mi = 0; mi < 2; mi++)
#pragma unroll
                for (int ni = 0; ni < 8; ni++) {
                    mma16816h(d[mi][ni], a_h[mi], b_h[ni]);
                    if (USE_LO) mma16816h(d[mi][ni], a_l[mi], b_h[ni]);
                }
        }
        __syncthreads();
    }

    // ---- epilogue ----------------------------------------------------------
#pragma unroll
    for (int mi = 0; mi < 2; mi++) {
#pragma unroll
        for (int ni = 0; ni < 8; ni++) {
            const int col = n0 + wn + ni * 8 + (lane & 3) * 2;
#pragma unroll
            for (int hf = 0; hf < 2; hf++) {
                const int row = m0 + wm + mi * 16 + (lane >> 2) + hf * 8;
                float vx = d[mi][ni][hf * 2 + 0];
                float vy = d[mi][ni][hf * 2 + 1];
                if (EPI == 1) {
                    vx += bias[col];     vy += bias[col + 1];
                    vx = (vx > 20.f) ? vx : log1pf(expf(vx));
                    vy = (vy > 20.f) ? vy : log1pf(expf(vy));
                }
                if (EPI == 2) {
                    const size_t o = (size_t)row * ldc + col;
                    if (col < N) {
                        C[o] = vx;
                        __half h, l; split1h(vx, h, l);
                        Chi[o] = h; Clo[o] = l;
                    }
                    if (col + 1 < N) {
                        C[o + 1] = vy;
                        __half h, l; split1h(vy, h, l);
                        Chi[o + 1] = h; Clo[o + 1] = l;
                    }
                } else if (EPI == 3) {
                    const size_t o = ((size_t)blockIdx.z * M + row) * ldc + col;
                    if (col < N)     C[o] = vx;
                    if (col + 1 < N) C[o + 1] = vy;
                } else {
                    float2 v2 = make_float2(vx, vy);
                    *(float2*)&C[(size_t)row * ldc + col] = v2;
                }
            }
        }
    }
}

// ================= split-K reduce for p96 ===================================
__global__ void p96_reduce_kernel()
{
    int i = blockIdx.x * 256 + threadIdx.x;
    if (i >= T_TOT * 96) return;
    const size_t SEG = (size_t)T_TOT * 96;
    float s = g_p96part[i] + g_p96part[SEG + i]
            + g_p96part[2 * SEG + i] + g_p96part[3 * SEG + i];
    g_p96[i] = s;
    __half h, l; split1h(s, h, l);
    g_p96h[i] = h; g_p96l[i] = l;
}

// ================= fused preprocessing (one launch) =========================
#define PRE_S0 (T_TOT * D_MODEL)
#define PRE_S1 (2 * D_INNER * D_MODEL)
#define PRE_S2 (D_MODEL * D_INNER)
#define PRE_S3 (D_INNER * DT_RANK)
#define PRE_S4 (96 * D_INNER)
#define PRE_TOT (PRE_S0 + PRE_S1 + PRE_S2 + PRE_S3 + PRE_S4)

__global__ void prep_kernel(const float* __restrict__ x,
                            const float* __restrict__ wi,
                            const float* __restrict__ wo,
                            const float* __restrict__ dtp,
                            const float* __restrict__ xp,
                            const float* __restrict__ bp,
                            const float* __restrict__ cp)
{
    int i = blockIdx.x * 256 + threadIdx.x;
    if (i < PRE_S0) { g_xh[i] = __float2half_rn(x[i]); return; }
    i -= PRE_S0;
    if (i < PRE_S1) { g_wih[i] = __float2half_rn(wi[i]); return; }
    i -= PRE_S1;
    if (i < PRE_S2) { g_oph[i] = __float2half_rn(wo[i]); return; }
    i -= PRE_S2;
    if (i < PRE_S3) { g_dtph[i] = __float2half_rn(dtp[i]); return; }
    i -= PRE_S3;
    if (i < PRE_S4) {
        int r = i / D_INNER, k = i % D_INNER;
        float v;
        if (r < 64)      v = xp[r * D_INNER + k];
        else if (r < 80) v = bp[(r - 64) * D_INNER + k];
        else             v = cp[(r - 80) * D_INNER + k];
        g_wcath[i] = __float2half_rn(v);
    }
}

// ================= conv + silu + hi/lo split ================================
__global__ void conv_silu_kernel(const float* __restrict__ conv_w,
                                 const float* __restrict__ conv_b)
{
    int idx = blockIdx.x * blockDim.x + threadIdx.x;
    if (idx >= T_TOT * D_INNER) return;
    int ch  = idx % D_INNER;
    int tok = idx / D_INNER;
    int b = tok / SEQ_L, l = tok % SEQ_L;
    float acc = conv_b[ch];
#pragma unroll
    for (int j = 0; j < 4; j++) {
        int ll = l - 3 + j;
        if (ll >= 0)
            acc = fmaf(conv_w[ch * 4 + j],
                       g_xz[(size_t)(b * SEQ_L + ll) * (2 * D_INNER) + ch], acc);
    }
    float s = acc / (1.f + expf(-acc));
    g_xconv[idx] = s;
    __half h, lo; split1h(s, h, lo);
    g_xch[idx] = h; g_xcl[idx] = lo;
}

// ---------------- selective scan + D-residual + gate ------------------------
#define TCHUNK 64
__global__ void __launch_bounds__(128) scan_kernel(
    const float* __restrict__ A_log,
    const float* __restrict__ Dp)
{
    __shared__ float Xs [TCHUNK][32];
    __shared__ float DTs[TCHUNK][32];
    __shared__ float Zs [TCHUNK][32];
    __shared__ float BCs[TCHUNK][32];
    __shared__ float Ys [TCHUNK][32];

    const int b      = blockIdx.x >> 6;
    const int chBase = (blockIdx.x & 63) * 32;
    const int tid = threadIdx.x;
    const int chl = tid >> 2;
    const int sg  = tid & 3;
    const int ch  = chBase + chl;

    const float a0 = -expf(A_log[ch * D_STATE + sg * 4 + 0]);
    const float a1 = -expf(A_log[ch * D_STATE + sg * 4 + 1]);
    const float a2 = -expf(A_log[ch * D_STATE + sg * 4 + 2]);
    const float a3 = -expf(A_log[ch * D_STATE + sg * 4 + 3]);
    float h0 = 0.f, h1 = 0.f, h2 = 0.f, h3 = 0.f;

    for (int t0 = 0; t0 < SEQ_L; t0 += TCHUNK) {
        for (int i = tid; i < TCHUNK * 32; i += 128) {
            int tt = i >> 5, c = i & 31;
            size_t tok = (size_t)(b * SEQ_L + t0 + tt);
            Xs [tt][c] = g_xconv[tok * D_INNER + chBase + c];
            DTs[tt][c] = g_dt   [tok * D_INNER + chBase + c];
            Zs [tt][c] = g_xz   [tok * (2 * D_INNER) + D_INNER + chBase + c];
            BCs[tt][c] = g_p96  [tok * 96 + 64 + c];
        }
        __syncthreads();

        for (int t = 0; t < TCHUNK; t++) {
            float x  = Xs [t][chl];
            float dt = DTs[t][chl];
            float dx = dt * x;
            float4 Bv = *(const float4*)&BCs[t][sg * 4];
            float4 Cv = *(const float4*)&BCs[t][16 + sg * 4];
            h0 = fmaf(fmaf(dt, a0, 1.f), h0, dx * Bv.x);
            h1 = fmaf(fmaf(dt, a1, 1.f), h1, dx * Bv.y);
            h2 = fmaf(fmaf(dt, a2, 1.f), h2, dx * Bv.z);
            h3 = fmaf(fmaf(dt, a3, 1.f), h3, dx * Bv.w);
            float yp =  h0 * Cv.x;
            yp = fmaf(h1, Cv.y, yp);
            yp = fmaf(h2, Cv.z, yp);
            yp = fmaf(h3, Cv.w, yp);
            yp += __shfl_xor_sync(0xffffffffu, yp, 1);
            yp += __shfl_xor_sync(0xffffffffu, yp, 2);
            if (sg == 0) Ys[t][chl] = yp;
        }
        __syncthreads();

        for (int i = tid; i < TCHUNK * 32; i += 128) {
            int tt = i >> 5, c = i & 31;
            size_t tok = (size_t)(b * SEQ_L + t0 + tt);
            float yv = fmaf(Dp[chBase + c], Xs[tt][c], Ys[tt][c]);
            float z  = Zs[tt][c];
            yv *= z / (1.f + expf(-z));
            g_yh[tok * D_INNER + chBase + c] = __float2half_rn(yv);
        }
        __syncthreads();
    }
}

// ================= launch ====================================================
extern "C" void kernel_launch(void* const* d_in, const int* in_sizes, int n_in,
                              void* d_out, int out_size)
{
    const float* x          = (const float*)d_in[0];
    const float* in_proj_w  = (const float*)d_in[1];
    const float* conv_w     = (const float*)d_in[2];
    const float* conv_b     = (const float*)d_in[3];
    const float* A_log      = (const float*)d_in[4];
    const float* Dp         = (const float*)d_in[5];
    const float* dt_proj_w  = (const float*)d_in[6];
    const float* dt_proj_b  = (const float*)d_in[7];
    const float* x_proj_w   = (const float*)d_in[8];
    const float* B_proj_w   = (const float*)d_in[9];
    const float* C_proj_w   = (const float*)d_in[10];
    const float* out_proj_w = (const float*)d_in[11];
    float* out = (float*)d_out;

    cudaFuncSetAttribute(gemm_mma<0,0>, cudaFuncAttributeMaxDynamicSharedMemorySize, GEMM_SMEM);
    cudaFuncSetAttribute(gemm_mma<1,1>, cudaFuncAttributeMaxDynamicSharedMemorySize, GEMM_SMEM);
    cudaFuncSetAttribute(gemm_mma<3,1>, cudaFuncAttributeMaxDynamicSharedMemorySize, GEMM_SMEM);

    float *xz, *p96part, *dtb;
    __half *xh, *wih, *xch, *xcl, *wcath;
    __half *p96h, *p96l, *dtph, *yh, *oph;
    cudaGetSymbolAddress((void**)&xz,      g_xz);
    cudaGetSymbolAddress((void**)&p96part, g_p96part);
    cudaGetSymbolAddress((void**)&dtb,     g_dt);
    cudaGetSymbolAddress((void**)&xh,      g_xh);
    cudaGetSymbolAddress((void**)&wih,     g_wih);
    cudaGetSymbolAddress((void**)&xch,     g_xch);
    cudaGetSymbolAddress((void**)&xcl,     g_xcl);
    cudaGetSymbolAddress((void**)&wcath,   g_wcath);
    cudaGetSymbolAddress((void**)&p96h,    g_p96h);
    cudaGetSymbolAddress((void**)&p96l,    g_p96l);
    cudaGetSymbolAddress((void**)&dtph,    g_dtph);
    cudaGetSymbolAddress((void**)&yh,      g_yh);
    cudaGetSymbolAddress((void**)&oph,     g_oph);

    // 0) fused preprocessing
    prep_kernel<<<(PRE_TOT + 255) / 256, 256>>>(x, in_proj_w, out_proj_w,
                                                dt_proj_w, x_proj_w, B_proj_w, C_proj_w);

    // 1) in_proj (single 1-term fp16 GEMM over the full 4096 output)
    {
        dim3 grid((2 * D_INNER) / 128, T_TOT / 128);
        gemm_mma<0,0><<<grid, 256, GEMM_SMEM>>>(xh, nullptr, D_MODEL, wih, D_MODEL,
                                                xz, 2 * D_INNER, T_TOT, 2 * D_INNER, D_MODEL,
                                                nullptr, nullptr, nullptr);
    }
    // 2) conv + silu (+ hi/lo split)
    conv_silu_kernel<<<(T_TOT * D_INNER + 255) / 256, 256>>>(conv_w, conv_b);

    // 3) p96 partials (split-K x4, 2-term A), then reduce (fp32 + hi/lo)
    {
        dim3 grid(1, T_TOT / 128, KSPLIT);
        gemm_mma<3,1><<<grid, 256, GEMM_SMEM>>>(xch, xcl, D_INNER, wcath, D_INNER,
                                                p96part, 96, T_TOT, 96, KSLICE,
                                                nullptr, nullptr, nullptr);
        p96_reduce_kernel<<<(T_TOT * 96 + 255) / 256, 256>>>();
    }
    // 4) dt = softplus(dtr @ dt_proj_w^T + b)  (2-term A)
    {
        dim3 grid(D_INNER / 128, T_TOT / 128);
        gemm_mma<1,1><<<grid, 256, GEMM_SMEM>>>(p96h, p96l, 96, dtph, DT_RANK,
                                                dtb, D_INNER, T_TOT, D_INNER, DT_RANK,
                                                dt_proj_b, nullptr, nullptr);
    }
    // 5) scan
    scan_kernel<<<B_SZ * (D_INNER / 32), 128>>>(A_log, Dp);

    // 6) out_proj (1-term)
    {
        dim3 grid(D_MODEL / 128, T_TOT / 128);
        gemm_mma<0,0><<<grid, 256, GEMM_SMEM>>>(yh, nullptr, D_INNER, oph, D_INNER,
                                                out, D_MODEL, T_TOT, D_MODEL, D_INNER,
                                                nullptr, nullptr, nullptr);
    }
}

// round 15
// speedup vs baseline: 1.5420x; 1.0073x over previous
#include <cuda_runtime.h>
#include <cuda_fp16.h>
#include <math.h>
#include <stdint.h>

#define B_SZ    2
#define SEQ_L   2048
#define D_MODEL 1024
#define D_STATE 16
#define D_INNER 2048
#define DT_RANK 64
#define T_TOT   (B_SZ * SEQ_L)          // 4096 tokens
#define KSPLIT  4
#define KSLICE  (D_INNER / KSPLIT)      // 512

// ---------------- fp32 scratch ----------------------------------------------
__device__ float g_xz[(size_t)T_TOT * 2 * D_INNER];   // in_proj out (x_in | z)
__device__ float g_xconv[(size_t)T_TOT * D_INNER];
__device__ float g_p96[(size_t)T_TOT * 96];           // [dtr(64)|B(16)|C(16)]
__device__ float g_p96part[(size_t)KSPLIT * T_TOT * 96];
__device__ float g_dt[(size_t)T_TOT * D_INNER];

// ---------------- fp16 scratch ----------------------------------------------
__device__ __half g_xh[(size_t)T_TOT * D_MODEL];
__device__ __half g_wih[(size_t)2*D_INNER*D_MODEL];
__device__ __half g_xch[(size_t)T_TOT * D_INNER], g_xcl[(size_t)T_TOT * D_INNER];
__device__ __half g_wcath[96 * D_INNER];
__device__ __half g_p96h[(size_t)T_TOT * 96],     g_p96l[(size_t)T_TOT * 96];
__device__ __half g_dtph[D_INNER * DT_RANK];
__device__ __half g_yh[(size_t)T_TOT * D_INNER];
__device__ __half g_oph[(size_t)D_MODEL*D_INNER];

// ================= helpers ==================================================
__device__ __forceinline__ uint32_t smem_u32(const void* p) {
    uint32_t a;
    asm("{ .reg .u64 t; cvta.to.shared.u64 t, %1; cvt.u32.u64 %0, t; }" : "=r"(a) : "l"(p));
    return a;
}
__device__ __forceinline__ void cp16(uint32_t dst, const void* src, uint32_t sz) {
    asm volatile("cp.async.cg.shared.global [%0], [%1], 16, %2;" :: "r"(dst), "l"(src), "r"(sz) : "memory");
}
#define CP_COMMIT()  asm volatile("cp.async.commit_group;" ::: "memory")

__device__ __forceinline__ void ldsm4(uint32_t& r0, uint32_t& r1, uint32_t& r2, uint32_t& r3, uint32_t a) {
    asm volatile("ldmatrix.sync.aligned.m8n8.x4.shared.b16 {%0,%1,%2,%3}, [%4];"
                 : "=r"(r0), "=r"(r1), "=r"(r2), "=r"(r3) : "r"(a));
}
__device__ __forceinline__ void mma16816h(float* d, const uint32_t* a, const uint32_t* b) {
    asm volatile("mma.sync.aligned.m16n8k16.row.col.f32.f16.f16.f32 "
                 "{%0,%1,%2,%3}, {%4,%5,%6,%7}, {%8,%9}, {%0,%1,%2,%3};"
                 : "+f"(d[0]), "+f"(d[1]), "+f"(d[2]), "+f"(d[3])
                 : "r"(a[0]), "r"(a[1]), "r"(a[2]), "r"(a[3]), "r"(b[0]), "r"(b[1]));
}
__device__ __forceinline__ void split1h(float v, __half& h, __half& l) {
    h = __float2half_rn(v);
    l = __float2half_rn(v - __half2float(h));
}

// ================= fp16 HMMA GEMM (compile-time A-lo term, 2-stage pipe) ====
//  C[M,N] = (Ah[+Al])[M,K] * Bh[N,K]^T
//  EPI 0: fp32 | 1: softplus(acc + bias[n]) | 2: fp32 + hi/lo fp16 (guarded N)
//  EPI 3: split-K partials -> C[(blockIdx.z*M + row)*ldc + col] (guarded N)
//  smem: 2 stages x (Ah|Al|Bh) x (128 rows x 144B) = 110592 -> 2 CTAs/SM
#define RS     144
#define MATB   (128 * RS)       // 18432
#define STG    (3 * MATB)       // 55296
static const int GEMM_SMEM = 2 * STG;   // 110592

template<int EPI, int USE_LO>
__global__ void __launch_bounds__(256) gemm_mma(
    const __half* __restrict__ Ah, const __half* __restrict__ Al, int lda,
    const __half* __restrict__ Bh, int ldb,
    float* __restrict__ C, int ldc, int M, int N, int K,
    const float* __restrict__ bias,
    __half* __restrict__ Chi, __half* __restrict__ Clo)
{
    extern __shared__ __align__(128) char ds[];
    const uint32_t sb = smem_u32(ds);
    const int tid = threadIdx.x, wid = tid >> 5, lane = tid & 31;
    const int m0 = blockIdx.y * 128, n0 = blockIdx.x * 128;
    const int wm = (wid & 3) * 32;
    const int wn = (wid >> 2) * 64;
    const int nbv = min(128, N - n0);
    const int NC = K >> 6;

    if (EPI == 3) {                    // split-K: this CTA covers one K-slice
        const int koff = blockIdx.z * K;
        Ah += koff; if (USE_LO) Al += koff; Bh += koff;
    }

    float d[2][8][4];
#pragma unroll
    for (int i = 0; i < 2; i++)
#pragma unroll
        for (int j = 0; j < 8; j++)
#pragma unroll
            for (int q = 0; q < 4; q++) d[i][j][q] = 0.f;

    constexpr int NCP = USE_LO ? 3072 : 2048;   // cp.async slots per stage
    auto load_stage = [&](int s, int c) {
        const int k0 = c << 6;
        const uint32_t base = sb + s * STG;
        for (int i = tid; i < NCP; i += 256) {
            const int mat = i >> 10;
            const int r   = (i >> 3) & 127;
            const int seg = i & 7;
            const __half* mp; int ld, gr; uint32_t sz = 16; uint32_t moff;
            if (mat == 0) { mp = Ah; ld = lda; gr = m0 + r; moff = 0; }
            else if (USE_LO && mat == 1) { mp = Al; ld = lda; gr = m0 + r; moff = MATB; }
            else { mp = Bh; ld = ldb; gr = n0 + r; moff = 2 * MATB;
                   if (r >= nbv) { sz = 0; gr = n0; } }
            const uint32_t dst = base + moff + r * RS + seg * 16;
            cp16(dst, mp + (size_t)gr * ld + k0 + seg * 8, sz);
        }
        CP_COMMIT();
    };

    load_stage(0, 0);

    for (int c = 0; c < NC; c++) {
        const int s = c & 1;
        if (c + 1 < NC) {
            load_stage(s ^ 1, c + 1);
            asm volatile("cp.async.wait_group 1;" ::: "memory");
        } else {
            asm volatile("cp.async.wait_group 0;" ::: "memory");
        }
        __syncthreads();

        const uint32_t base = sb + s * STG;
        const uint32_t aH = base, aL = base + MATB, bH = base + 2 * MATB;
#pragma unroll
        for (int ks = 0; ks < 4; ks++) {
            const int k0 = ks * 16;
            uint32_t a_h[2][4], a_l[2][4], b_h[8][2];
            const uint32_t aoff = (wm + (lane & 15)) * RS + (k0 + ((lane >> 4) << 3)) * 2;
#pragma unroll
            for (int mi = 0; mi < 2; mi++) {
                ldsm4(a_h[mi][0], a_h[mi][1], a_h[mi][2], a_h[mi][3], aH + aoff + mi * 16 * RS);
                if (USE_LO)
                    ldsm4(a_l[mi][0], a_l[mi][1], a_l[mi][2], a_l[mi][3], aL + aoff + mi * 16 * RS);
            }
            const int g = lane >> 3;
            const uint32_t boff = (wn + ((g >> 1) << 3) + (lane & 7)) * RS + (k0 + ((g & 1) << 3)) * 2;
#pragma unroll
            for (int ng = 0; ng < 4; ng++)
                ldsm4(b_h[ng*2][0], b_h[ng*2][1], b_h[ng*2+1][0], b_h[ng*2+1][1], bH + boff + ng * 16 * RS);
#pragma unroll
            for (int mi = 0; mi < 2; mi++)
#pragma unroll
                for (int ni = 0; ni < 8; ni++) {
                    mma16816h(d[mi][ni], a_h[mi], b_h[ni]);
                    if (USE_LO) mma16816h(d[mi][ni], a_l[mi], b_h[ni]);
                }
        }
        __syncthreads();
    }

    // ---- epilogue ----------------------------------------------------------
#pragma unroll
    for (int mi = 0; mi < 2; mi++) {
#pragma unroll
        for (int ni = 0; ni < 8; ni++) {
            const int col = n0 + wn + ni * 8 + (lane & 3) * 2;
#pragma unroll
            for (int hf = 0; hf < 2; hf++) {
                const int row = m0 + wm + mi * 16 + (lane >> 2) + hf * 8;
                float vx = d[mi][ni][hf * 2 + 0];
                float vy = d[mi][ni][hf * 2 + 1];
                if (EPI == 1) {
                    vx += bias[col];     vy += bias[col + 1];
                    vx = (vx > 20.f) ? vx : log1pf(expf(vx));
                    vy = (vy > 20.f) ? vy : log1pf(expf(vy));
                }
                if (EPI == 2) {
                    const size_t o = (size_t)row * ldc + col;
                    if (col < N) {
                        C[o] = vx;
                        __half h, l; split1h(vx, h, l);
                        Chi[o] = h; Clo[o] = l;
                    }
                    if (col + 1 < N) {
                        C[o + 1] = vy;
                        __half h, l; split1h(vy, h, l);
                        Chi[o + 1] = h; Clo[o + 1] = l;
                    }
                } else if (EPI == 3) {
                    const size_t o = ((size_t)blockIdx.z * M + row) * ldc + col;
                    if (col < N)     C[o] = vx;
                    if (col + 1 < N) C[o + 1] = vy;
                } else {
                    float2 v2 = make_float2(vx, vy);
                    *(float2*)&C[(size_t)row * ldc + col] = v2;
                }
            }
        }
    }
}

// ================= split-K reduce for p96 ===================================
__global__ void p96_reduce_kernel()
{
    int i = blockIdx.x * 256 + threadIdx.x;
    if (i >= T_TOT * 96) return;
    const size_t SEG = (size_t)T_TOT * 96;
    float s = g_p96part[i] + g_p96part[SEG + i]
            + g_p96part[2 * SEG + i] + g_p96part[3 * SEG + i];
    g_p96[i] = s;
    __half h, l; split1h(s, h, l);
    g_p96h[i] = h; g_p96l[i] = l;
}

// ================= fused preprocessing (one launch) =========================
#define PRE_S0 (T_TOT * D_MODEL)
#define PRE_S1 (2 * D_INNER * D_MODEL)
#define PRE_S2 (D_MODEL * D_INNER)
#define PRE_S3 (D_INNER * DT_RANK)
#define PRE_S4 (96 * D_INNER)
#define PRE_TOT (PRE_S0 + PRE_S1 + PRE_S2 + PRE_S3 + PRE_S4)

__global__ void prep_kernel(const float* __restrict__ x,
                            const float* __restrict__ wi,
                            const float* __restrict__ wo,
                            const float* __restrict__ dtp,
                            const float* __restrict__ xp,
                            const float* __restrict__ bp,
                            const float* __restrict__ cp)
{
    int i = blockIdx.x * 256 + threadIdx.x;
    if (i < PRE_S0) { g_xh[i] = __float2half_rn(x[i]); return; }
    i -= PRE_S0;
    if (i < PRE_S1) { g_wih[i] = __float2half_rn(wi[i]); return; }
    i -= PRE_S1;
    if (i < PRE_S2) { g_oph[i] = __float2half_rn(wo[i]); return; }
    i -= PRE_S2;
    if (i < PRE_S3) { g_dtph[i] = __float2half_rn(dtp[i]); return; }
    i -= PRE_S3;
    if (i < PRE_S4) {
        int r = i / D_INNER, k = i % D_INNER;
        float v;
        if (r < 64)      v = xp[r * D_INNER + k];
        else if (r < 80) v = bp[(r - 64) * D_INNER + k];
        else             v = cp[(r - 80) * D_INNER + k];
        g_wcath[i] = __float2half_rn(v);
    }
}

// ================= conv + silu + hi/lo split ================================
__global__ void conv_silu_kernel(const float* __restrict__ conv_w,
                                 const float* __restrict__ conv_b)
{
    int idx = blockIdx.x * blockDim.x + threadIdx.x;
    if (idx >= T_TOT * D_INNER) return;
    int ch  = idx % D_INNER;
    int tok = idx / D_INNER;
    int b = tok / SEQ_L, l = tok % SEQ_L;
    float acc = conv_b[ch];
#pragma unroll
    for (int j = 0; j < 4; j++) {
        int ll = l - 3 + j;
        if (ll >= 0)
            acc = fmaf(conv_w[ch * 4 + j],
                       g_xz[(size_t)(b * SEQ_L + ll) * (2 * D_INNER) + ch], acc);
    }
    float s = acc / (1.f + expf(-acc));
    g_xconv[idx] = s;
    __half h, lo; split1h(s, h, lo);
    g_xch[idx] = h; g_xcl[idx] = lo;
}

// ---------------- selective scan + D-residual + gate ------------------------
#define TCHUNK 64
__global__ void __launch_bounds__(128) scan_kernel(
    const float* __restrict__ A_log,
    const float* __restrict__ Dp)
{
    __shared__ float Xs [TCHUNK][32];
    __shared__ float DTs[TCHUNK][32];
    __shared__ float Zs [TCHUNK][32];
    __shared__ float BCs[TCHUNK][32];
    __shared__ float Ys [TCHUNK][32];

    const int b      = blockIdx.x >> 6;
    const int chBase = (blockIdx.x & 63) * 32;
    const int tid = threadIdx.x;
    const int chl = tid >> 2;
    const int sg  = tid & 3;
    const int ch  = chBase + chl;

    const float a0 = -expf(A_log[ch * D_STATE + sg * 4 + 0]);
    const float a1 = -expf(A_log[ch * D_STATE + sg * 4 + 1]);
    const float a2 = -expf(A_log[ch * D_STATE + sg * 4 + 2]);
    const float a3 = -expf(A_log[ch * D_STATE + sg * 4 + 3]);
    float h0 = 0.f, h1 = 0.f, h2 = 0.f, h3 = 0.f;

    for (int t0 = 0; t0 < SEQ_L; t0 += TCHUNK) {
        for (int i = tid; i < TCHUNK * 32; i += 128) {
            int tt = i >> 5, c = i & 31;
            size_t tok = (size_t)(b * SEQ_L + t0 + tt);
            Xs [tt][c] = g_xconv[tok * D_INNER + chBase + c];
            DTs[tt][c] = g_dt   [tok * D_INNER + chBase + c];
            Zs [tt][c] = g_xz   [tok * (2 * D_INNER) + D_INNER + chBase + c];
            BCs[tt][c] = g_p96  [tok * 96 + 64 + c];
        }
        __syncthreads();

        for (int t = 0; t < TCHUNK; t++) {
            float x  = Xs [t][chl];
            float dt = DTs[t][chl];
            float dx = dt * x;
            float4 Bv = *(const float4*)&BCs[t][sg * 4];
            float4 Cv = *(const float4*)&BCs[t][16 + sg * 4];
            h0 = fmaf(fmaf(dt, a0, 1.f), h0, dx * Bv.x);
            h1 = fmaf(fmaf(dt, a1, 1.f), h1, dx * Bv.y);
            h2 = fmaf(fmaf(dt, a2, 1.f), h2, dx * Bv.z);
            h3 = fmaf(fmaf(dt, a3, 1.f), h3, dx * Bv.w);
            float yp =  h0 * Cv.x;
            yp = fmaf(h1, Cv.y, yp);
            yp = fmaf(h2, Cv.z, yp);
            yp = fmaf(h3, Cv.w, yp);
            yp += __shfl_xor_sync(0xffffffffu, yp, 1);
            yp += __shfl_xor_sync(0xffffffffu, yp, 2);
            if (sg == 0) Ys[t][chl] = yp;
        }
        __syncthreads();

        for (int i = tid; i < TCHUNK * 32; i += 128) {
            int tt = i >> 5, c = i & 31;
            size_t tok = (size_t)(b * SEQ_L + t0 + tt);
            float yv = fmaf(Dp[chBase + c], Xs[tt][c], Ys[tt][c]);
            float z  = Zs[tt][c];
            yv *= z / (1.f + expf(-z));
            g_yh[tok * D_INNER + chBase + c] = __float2half_rn(yv);
        }
        __syncthreads();
    }
}

// ================= launch ====================================================
extern "C" void kernel_launch(void* const* d_in, const int* in_sizes, int n_in,
                              void* d_out, int out_size)
{
    const float* x          = (const float*)d_in[0];
    const float* in_proj_w  = (const float*)d_in[1];
    const float* conv_w     = (const float*)d_in[2];
    const float* conv_b     = (const float*)d_in[3];
    const float* A_log      = (const float*)d_in[4];
    const float* Dp         = (const float*)d_in[5];
    const float* dt_proj_w  = (const float*)d_in[6];
    const float* dt_proj_b  = (const float*)d_in[7];
    const float* x_proj_w   = (const float*)d_in[8];
    const float* B_proj_w   = (const float*)d_in[9];
    const float* C_proj_w   = (const float*)d_in[10];
    const float* out_proj_w = (const float*)d_in[11];
    float* out = (float*)d_out;

    cudaFuncSetAttribute(gemm_mma<0,0>, cudaFuncAttributeMaxDynamicSharedMemorySize, GEMM_SMEM);
    cudaFuncSetAttribute(gemm_mma<1,1>, cudaFuncAttributeMaxDynamicSharedMemorySize, GEMM_SMEM);
    cudaFuncSetAttribute(gemm_mma<3,1>, cudaFuncAttributeMaxDynamicSharedMemorySize, GEMM_SMEM);

    float *xz, *p96part, *dtb;
    __half *xh, *wih, *xch, *xcl, *wcath;
    __half *p96h, *p96l, *dtph, *yh, *oph;
    cudaGetSymbolAddress((void**)&xz,      g_xz);
    cudaGetSymbolAddress((void**)&p96part, g_p96part);
    cudaGetSymbolAddress((void**)&dtb,     g_dt);
    cudaGetSymbolAddress((void**)&xh,      g_xh);
    cudaGetSymbolAddress((void**)&wih,     g_wih);
    cudaGetSymbolAddress((void**)&xch,     g_xch);
    cudaGetSymbolAddress((void**)&xcl,     g_xcl);
    cudaGetSymbolAddress((void**)&wcath,   g_wcath);
    cudaGetSymbolAddress((void**)&p96h,    g_p96h);
    cudaGetSymbolAddress((void**)&p96l,    g_p96l);
    cudaGetSymbolAddress((void**)&dtph,    g_dtph);
    cudaGetSymbolAddress((void**)&yh,      g_yh);
    cudaGetSymbolAddress((void**)&oph,     g_oph);

    // side stream + fork/join events (host objects only; a handful of
    // kernel_launch invocations total, so per-call creation is fine)
    cudaStream_t s2;
    cudaStreamCreateWithFlags(&s2, cudaStreamNonBlocking);
    cudaEvent_t eFork, eJoin;
    cudaEventCreateWithFlags(&eFork, cudaEventDisableTiming);
    cudaEventCreateWithFlags(&eJoin, cudaEventDisableTiming);

    // 0) fused preprocessing (main stream)
    prep_kernel<<<(PRE_TOT + 255) / 256, 256>>>(x, in_proj_w, out_proj_w,
                                                dt_proj_w, x_proj_w, B_proj_w, C_proj_w);

    // fork: z-half GEMM runs on s2, overlapped with conv -> p96 -> reduce -> dt
    cudaEventRecord(eFork, 0);
    cudaStreamWaitEvent(s2, eFork, 0);

    // 1a) in_proj x-half (main stream): xz[:, 0:2048]
    {
        dim3 grid(D_INNER / 128, T_TOT / 128);
        gemm_mma<0,0><<<grid, 256, GEMM_SMEM>>>(xh, nullptr, D_MODEL, wih, D_MODEL,
                                                xz, 2 * D_INNER, T_TOT, D_INNER, D_MODEL,
                                                nullptr, nullptr, nullptr);
    }
    // 1b) in_proj z-half (side stream): xz[:, 2048:4096] — needed only by scan
    {
        dim3 grid(D_INNER / 128, T_TOT / 128);
        gemm_mma<0,0><<<grid, 256, GEMM_SMEM, s2>>>(xh, nullptr, D_MODEL,
                                                    wih + (size_t)D_INNER * D_MODEL, D_MODEL,
                                                    xz + D_INNER, 2 * D_INNER, T_TOT, D_INNER, D_MODEL,
                                                    nullptr, nullptr, nullptr);
    }
    cudaEventRecord(eJoin, s2);

    // 2) conv + silu (+ hi/lo split) — depends on x-half only
    conv_silu_kernel<<<(T_TOT * D_INNER + 255) / 256, 256>>>(conv_w, conv_b);

    // 3) p96 partials (split-K x4, 2-term A), then reduce (fp32 + hi/lo)
    {
        dim3 grid(1, T_TOT / 128, KSPLIT);
        gemm_mma<3,1><<<grid, 256, GEMM_SMEM>>>(xch, xcl, D_INNER, wcath, D_INNER,
                                                p96part, 96, T_TOT, 96, KSLICE,
                                                nullptr, nullptr, nullptr);
        p96_reduce_kernel<<<(T_TOT * 96 + 255) / 256, 256>>>();
    }
    // 4) dt = softplus(dtr @ dt_proj_w^T + b)  (2-term A)
    {
        dim3 grid(D_INNER / 128, T_TOT / 128);
        gemm_mma<1,1><<<grid, 256, GEMM_SMEM>>>(p96h, p96l, 96, dtph, DT_RANK,
                                                dtb, D_INNER, T_TOT, D_INNER, DT_RANK,
                                                dt_proj_b, nullptr, nullptr);
    }

    // join: scan needs the z-half
    cudaStreamWaitEvent(0, eJoin, 0);

    // 5) scan
    scan_kernel<<<B_SZ * (D_INNER / 32), 128>>>(A_log, Dp);

    // 6) out_proj (1-term)
    {
        dim3 grid(D_MODEL / 128, T_TOT / 128);
        gemm_mma<0,0><<<grid, 256, GEMM_SMEM>>>(yh, nullptr, D_INNER, oph, D_INNER,
                                                out, D_MODEL, T_TOT, D_MODEL, D_INNER,
                                                nullptr, nullptr, nullptr);
    }
}